// round 13
// baseline (speedup 1.0000x reference)
#include <cuda_runtime.h>
#include <cuda_bf16.h>
#include <math.h>
#include <stdint.h>

#define NTOK  65536
#define DHALF 384
#define DFULL 768
#define LSZ   64
#define HSZ   64
#define RSZ   8

// ---------------- device scratch (static; no allocations) ----------------
__device__ int   g_cnt[RSZ];
__device__ float g_probsum[RSZ];
__device__ int   g_list[RSZ*NTOK];              // entry e = 2*n + slot
__device__ float g_gate[2*NTOK];                // gate weight per entry
__device__ float g_out[(size_t)2*NTOK*LSZ];     // gate-scaled softmax scores per entry
// pre-split, pre-swizzled Vl (ldmatrix layout, [r] blocks of 64 rows x 128B)
__device__ __align__(16) char g_VhSwz[RSZ*8192];
__device__ __align__(16) char g_VlSwz[RSZ*8192];
// pre-split, pre-swizzled U_w: [r][chunk c<12] blocks of 64 k-rows x 128B
__device__ __align__(16) char g_Wh[RSZ*12*8192];
__device__ __align__(16) char g_Wl[RSZ*12*8192];

// ---------------- helpers ----------------
__device__ __forceinline__ uint32_t packbf(float lo, float hi) {
    uint32_t d;
    asm("cvt.rn.bf16x2.f32 %0, %1, %2;" : "=r"(d) : "f"(hi), "f"(lo));
    return d;
}
__device__ __forceinline__ void split2(float x0, float x1, uint32_t& hp, uint32_t& lp) {
    hp = packbf(x0, x1);
    float h0 = __uint_as_float(hp << 16);
    float h1 = __uint_as_float(hp & 0xffff0000u);
    lp = packbf(x0 - h0, x1 - h1);
}
__device__ __forceinline__ void ldsm4(uint32_t r[4], uint32_t addr) {
    asm volatile("ldmatrix.sync.aligned.m8n8.x4.shared.b16 {%0,%1,%2,%3}, [%4];"
        : "=r"(r[0]), "=r"(r[1]), "=r"(r[2]), "=r"(r[3]) : "r"(addr));
}
__device__ __forceinline__ void ldsm4t(uint32_t r[4], uint32_t addr) {
    asm volatile("ldmatrix.sync.aligned.m8n8.x4.trans.shared.b16 {%0,%1,%2,%3}, [%4];"
        : "=r"(r[0]), "=r"(r[1]), "=r"(r[2]), "=r"(r[3]) : "r"(addr));
}
__device__ __forceinline__ void mma16816(float c[4], const uint32_t a[4],
                                         uint32_t b0, uint32_t b1) {
    asm volatile("mma.sync.aligned.m16n8k16.row.col.f32.bf16.bf16.f32 "
        "{%0,%1,%2,%3}, {%4,%5,%6,%7}, {%8,%9}, {%0,%1,%2,%3};"
        : "+f"(c[0]), "+f"(c[1]), "+f"(c[2]), "+f"(c[3])
        : "r"(a[0]), "r"(a[1]), "r"(a[2]), "r"(a[3]), "r"(b0), "r"(b1));
}
__device__ __forceinline__ void cp16(uint32_t dst, const void* src) {
    asm volatile("cp.async.ca.shared.global [%0], [%1], 16;" :: "r"(dst), "l"(src));
}

// ---------------- W presplit (+init): U_w -> bf16 hi/lo, swizzled ----------
__global__ __launch_bounds__(128) void wsplit_kernel(const float* __restrict__ Uw) {
    int bx = blockIdx.x;
    int r = bx / 12, c = bx % 12;
    int t = threadIdx.x;
    if (bx == 0 && t < RSZ) { g_cnt[t] = 0; g_probsum[t] = 0.f; }
    int wrow = t >> 1, whalf = t & 1;
    const float* src = Uw + ((size_t)r*DFULL + c*64 + wrow)*HSZ + whalf*32;
    char* dh = g_Wh + ((size_t)(r*12 + c))*8192;
    char* dl = g_Wl + ((size_t)(r*12 + c))*8192;
    uint32_t rowb = (uint32_t)(wrow*128 + whalf*64);
    uint32_t xorv = (uint32_t)(wrow & 7) << 4;
    #pragma unroll
    for (int q2 = 0; q2 < 4; q2++) {
        float4 v0 = ((const float4*)src)[2*q2];
        float4 v1 = ((const float4*)src)[2*q2 + 1];
        uint32_t h0,h1,h2,h3,l0,l1,l2,l3;
        split2(v0.x, v0.y, h0, l0); split2(v0.z, v0.w, h1, l1);
        split2(v1.x, v1.y, h2, l2); split2(v1.z, v1.w, h3, l3);
        uint32_t off = (rowb + q2*16) ^ xorv;
        *(uint4*)(dh + off) = make_uint4(h0,h1,h2,h3);
        *(uint4*)(dl + off) = make_uint4(l0,l1,l2,l3);
    }
}

// ---------------- Vl = l2norm(llm @ V_w[r] + V_b[r]); emit swizzled bf16 hi/lo -------
__global__ __launch_bounds__(64) void vl_kernel(const float* __restrict__ llm,
                                                const float* __restrict__ Vw,
                                                const float* __restrict__ Vb) {
    int l = blockIdx.x, r = blockIdx.y, h = threadIdx.x;
    __shared__ float lsm[DHALF];
    __shared__ float red[64];
    __shared__ float s_inv;
    for (int i = h; i < DHALF; i += 64) lsm[i] = llm[l*DHALF + i];
    __syncthreads();
    float acc = Vb[r*HSZ + h];
    const float* w = Vw + ((size_t)r*DHALF)*HSZ + h;
    #pragma unroll 8
    for (int d = 0; d < DHALF; d++) acc += lsm[d] * w[(size_t)d*HSZ];
    red[h] = acc*acc;
    __syncthreads();
    if (h == 0) {
        float ss = 0.f;
        #pragma unroll
        for (int i = 0; i < 64; i++) ss += red[i];
        s_inv = 1.f / fmaxf(sqrtf(ss), 1e-12f);
    }
    __syncthreads();
    float val = acc * s_inv;
    unsigned short hbits = __bfloat16_as_ushort(__float2bfloat16(val));
    float hf = __uint_as_float(((uint32_t)hbits) << 16);
    unsigned short lbits = __bfloat16_as_ushort(__float2bfloat16(val - hf));
    uint32_t off = (uint32_t)(h*128 + l*2) ^ ((uint32_t)(h & 7) << 4);
    *(unsigned short*)(g_VhSwz + r*8192 + off) = hbits;
    *(unsigned short*)(g_VlSwz + r*8192 + off) = lbits;
}

// ---------------- gate v5: lane = token; broadcast w; cp.async double buffer -------
#define GB 256
struct GateSmem {
    float Wt[RSZ][772];        // [r][k], warp-uniform reads (broadcast)
    float Xc[2][8][32][36];    // double-buffered per-warp x chunk (32 floats + pad)
    float pblk[8][RSZ];
    float bsm[RSZ];
    int   i1s[GB], i2s[GB];
    int   locs[2*GB];
    int   cnt2[16];
    int   bases[RSZ];
};

__global__ __launch_bounds__(256, 2) void gate_kernel(const float* __restrict__ posts,
                                                      const float* __restrict__ reas,
                                                      const float* __restrict__ gw,
                                                      const float* __restrict__ gb) {
    extern __shared__ char gsraw[];
    GateSmem& sh = *reinterpret_cast<GateSmem*>(gsraw);
    int t = threadIdx.x, lane = t & 31, w = t >> 5;
    int nblk = blockIdx.x * GB;
    int n = nblk + t;                       // this lane's token

    for (int i = t; i < DFULL*RSZ; i += 256) {
        int k = i >> 3, rr = i & 7;
        sh.Wt[rr][k] = gw[i];
    }
    if (t < RSZ) sh.bsm[t] = gb[t];

    uint32_t XcB = (uint32_t)__cvta_generic_to_shared(&sh.Xc[0][0][0][0]);
    int tokb = lane >> 3, fq = lane & 7;    // staging: 4 tokens x 8 float4 per phase

    auto stage = [&](int c, int buf) {
        const float* bsrc = (c < 12) ? posts : reas;
        int off = (c < 12) ? c*32 : (c - 12)*32;
        #pragma unroll
        for (int ii = 0; ii < 8; ii++) {
            int tok = ii*4 + tokb;
            const float* src = bsrc + (size_t)(nblk + w*32 + tok)*DHALF + off + 4*fq;
            uint32_t dst = XcB + (uint32_t)(((buf*8 + w)*32 + tok)*144 + 16*fq);
            cp16(dst, src);
        }
        asm volatile("cp.async.commit_group;" ::: "memory");
    };

    float acc[RSZ];
    #pragma unroll
    for (int r = 0; r < RSZ; r++) acc[r] = 0.f;

    stage(0, 0);
    __syncthreads();   // Wt/bsm ready (staging itself is warp-local via cp.async)

    for (int c = 0; c < 24; c++) {
        if (c + 1 < 24) {
            stage(c + 1, (c + 1) & 1);
            asm volatile("cp.async.wait_group 1;" ::: "memory");
        } else {
            asm volatile("cp.async.wait_group 0;" ::: "memory");
        }
        __syncwarp();
        int buf = c & 1;
        #pragma unroll
        for (int j4 = 0; j4 < 8; j4++) {
            float4 xv = *(const float4*)&sh.Xc[buf][w][lane][4*j4];
            #pragma unroll
            for (int r = 0; r < RSZ; r++) {
                float4 wv = *(const float4*)&sh.Wt[r][c*32 + 4*j4];
                acc[r] += xv.x*wv.x + xv.y*wv.y + xv.z*wv.z + xv.w*wv.w;
            }
        }
        __syncwarp();
    }

    float lg[RSZ];
    #pragma unroll
    for (int r = 0; r < RSZ; r++) lg[r] = acc[r] + sh.bsm[r];

    // serial top-2 (strict >, earlier index wins ties — matches jax top_k)
    float v1 = -1e30f, v2 = -1e30f; int i1 = 0, i2 = 0;
    #pragma unroll
    for (int r = 0; r < RSZ; r++) {
        if (lg[r] > v1)      { v2 = v1; i2 = i1; v1 = lg[r]; i1 = r; }
        else if (lg[r] > v2) { v2 = lg[r]; i2 = r; }
    }
    // softmax over 8 routers (aux probsum)
    float p[RSZ], s = 0.f;
    #pragma unroll
    for (int r = 0; r < RSZ; r++) { p[r] = expf(lg[r] - v1); s += p[r]; }
    float invs = 1.f / s;
    #pragma unroll
    for (int r = 0; r < RSZ; r++) {
        float q = p[r] * invs;
        q += __shfl_xor_sync(0xffffffffu, q, 16);
        q += __shfl_xor_sync(0xffffffffu, q, 8);
        q += __shfl_xor_sync(0xffffffffu, q, 4);
        q += __shfl_xor_sync(0xffffffffu, q, 2);
        q += __shfl_xor_sync(0xffffffffu, q, 1);
        if (lane == 0) sh.pblk[w][r] = q;
    }
    float g0 = 1.f / (1.f + expf(v2 - v1));
    g_gate[2*n]   = g0;
    g_gate[2*n+1] = 1.f - g0;
    sh.i1s[t] = i1; sh.i2s[t] = i2;
    __syncthreads();

    // stable compaction, 16 scanners (r, half)
    if (t < 16) {
        int r = t & 7, h = t >> 3;
        int c = 0;
        for (int e = h*GB; e < (h + 1)*GB; e++) {
            int rid = (e & 1) ? sh.i2s[e >> 1] : sh.i1s[e >> 1];
            if (rid == r) sh.locs[e] = c++;
        }
        sh.cnt2[t] = c;
    }
    __syncthreads();
    if (t < RSZ) sh.bases[t] = atomicAdd(&g_cnt[t], sh.cnt2[t] + sh.cnt2[t + 8]);
    __syncthreads();
    #pragma unroll
    for (int pass = 0; pass < 2; pass++) {
        int e = t + pass*256;
        int rid = (e & 1) ? sh.i2s[e >> 1] : sh.i1s[e >> 1];
        int off = sh.bases[rid] + sh.locs[e] + ((e >= GB) ? sh.cnt2[rid] : 0);
        g_list[rid*NTOK + off] = 2*(nblk + (e >> 1)) + (e & 1);
    }
    if (t < RSZ) {
        float sm = 0.f;
        #pragma unroll
        for (int wi = 0; wi < 8; wi++) sm += sh.pblk[wi][t];
        atomicAdd(&g_probsum[t], sm);
    }
}

// ---------------- proj: bf16x3 tensor MMA, fully-async staging pipeline ----------
struct ProjSmem {
    union {
        struct {
            char Ah[16384]; char Al[16384];
            char Wh[2][8192]; char Wl[2][8192];
            float Xf[128][68];                 // raw fp32 X rows (pad 68 -> conflict-free)
        } m;
        struct { char Uh[16384]; char Ul[16384]; char Vh[8192]; char Vl[8192]; } e;
    } u;
    int   el[128];
    float gwv[128];
    float bs[64];
};

__global__ __launch_bounds__(128, 2) void proj_kernel(const float* __restrict__ posts,
                                                      const float* __restrict__ reas,
                                                      const float* __restrict__ Ub) {
    int r = blockIdx.y;
    int cnt = g_cnt[r];
    int base = blockIdx.x * 128;
    if (base >= cnt) return;

    extern __shared__ char smraw[];
    ProjSmem& sh = *reinterpret_cast<ProjSmem*>(smraw);

    int t = threadIdx.x, lane = t & 31, w = t >> 5;
    const int R0 = 32*w;
    const int g  = lane >> 2;
    const int tq = lane & 3;

    {
        int i = base + t;
        int e = (i < cnt) ? g_list[r*NTOK + i] : g_list[r*NTOK + base];
        sh.el[t] = e;
        sh.gwv[t] = g_gate[e];
    }
    if (t < 64) sh.bs[t] = Ub[r*HSZ + t];
    __syncthreads();

    uint32_t AhB = (uint32_t)__cvta_generic_to_shared(sh.u.m.Ah);
    uint32_t AlB = (uint32_t)__cvta_generic_to_shared(sh.u.m.Al);
    uint32_t WhB = (uint32_t)__cvta_generic_to_shared(&sh.u.m.Wh[0][0]);
    uint32_t WlB = (uint32_t)__cvta_generic_to_shared(&sh.u.m.Wl[0][0]);
    uint32_t XfB = (uint32_t)__cvta_generic_to_shared(&sh.u.m.Xf[0][0]);

    const int half = lane >> 4, fq = lane & 15;
    const int xn_self = sh.el[t] >> 1;      // thread t stages row t

    auto stageX = [&](int c) {
        const float* bsrc = (c < 6) ? posts : reas;
        int off_in = (c < 6) ? c*64 : (c - 6)*64;
        const float* src = bsrc + (size_t)xn_self*DHALF + off_in;
        uint32_t dst = XfB + (uint32_t)t*272;
        #pragma unroll
        for (int q = 0; q < 16; q++) cp16(dst + 16*q, src + 4*q);
    };
    auto stageW = [&](int c) {
        int buf = c & 1;
        const char* srcH = g_Wh + ((size_t)(r*12 + c))*8192 + t*64;
        const char* srcL = g_Wl + ((size_t)(r*12 + c))*8192 + t*64;
        uint32_t dH = WhB + buf*8192 + t*64;
        uint32_t dL = WlB + buf*8192 + t*64;
        #pragma unroll
        for (int q = 0; q < 4; q++) {
            cp16(dH + 16*q, srcH + 16*q);
            cp16(dL + 16*q, srcL + 16*q);
        }
    };

    float acc[2][8][4];
    #pragma unroll
    for (int T = 0; T < 2; T++)
        #pragma unroll
        for (int j = 0; j < 8; j++)
            #pragma unroll
            for (int q = 0; q < 4; q++) acc[T][j][q] = 0.f;

    stageX(0); stageW(0);
    asm volatile("cp.async.commit_group;" ::: "memory");

    for (int c = 0; c < 12; c++) {
        asm volatile("cp.async.wait_group 0;" ::: "memory");
        __syncthreads();            // everyone's cp landed; previous mma done
        // ---- convert phase: Xf (fp32, smem) -> Ah/Al bf16 hi/lo, swizzled ----
        #pragma unroll
        for (int i = 0; i < 16; i++) {
            int row = 32*w + 2*i + half;
            float4 v = *(const float4*)&sh.u.m.Xf[row][4*fq];
            uint32_t hp, lp, hp2, lp2;
            split2(v.x, v.y, hp, lp);
            split2(v.z, v.w, hp2, lp2);
            uint32_t off = ((uint32_t)row*128 + fq*8) ^ ((uint32_t)(row & 7) << 4);
            *(uint2*)(sh.u.m.Ah + off) = make_uint2(hp, hp2);
            *(uint2*)(sh.u.m.Al + off) = make_uint2(lp, lp2);
        }
        __syncthreads();            // Ah/Al ready; Xf consumed
        if (c + 1 < 12) {
            stageX(c + 1); stageW(c + 1);
            asm volatile("cp.async.commit_group;" ::: "memory");
        }
        // ---- tensor mainloop: 4 k16-steps, bf16x3, B shared across 2 m-tiles ----
        uint32_t wbuf = (uint32_t)(c & 1) * 8192;
        #pragma unroll
        for (int kk = 0; kk < 4; kk++) {
            int arow = R0 + (lane & 15);
            uint32_t asel = (uint32_t)(2*kk + (lane >> 4))*16;
            uint32_t aoff0 = ((uint32_t)arow*128 + asel) ^ ((uint32_t)(arow & 7) << 4);
            int arow1 = arow + 16;
            uint32_t aoff1 = ((uint32_t)arow1*128 + asel) ^ ((uint32_t)(arow1 & 7) << 4);
            uint32_t ah0[4], al0[4], ah1[4], al1[4];
            ldsm4(ah0, AhB + aoff0); ldsm4(al0, AlB + aoff0);
            ldsm4(ah1, AhB + aoff1); ldsm4(al1, AlB + aoff1);
            int krow = 16*kk + (lane & 15);
            uint32_t bxor = (uint32_t)(krow & 7) << 4;
            #pragma unroll
            for (int f = 0; f < 4; f++) {
                uint32_t boff = (((uint32_t)krow*128 + (2*f + (lane >> 4))*16) ^ bxor) + wbuf;
                uint32_t bh[4], bl[4];
                ldsm4t(bh, WhB + boff);
                mma16816(acc[0][2*f],     ah0, bh[0], bh[1]);
                mma16816(acc[0][2*f + 1], ah0, bh[2], bh[3]);
                mma16816(acc[0][2*f],     al0, bh[0], bh[1]);
                mma16816(acc[0][2*f + 1], al0, bh[2], bh[3]);
                mma16816(acc[1][2*f],     ah1, bh[0], bh[1]);
                mma16816(acc[1][2*f + 1], ah1, bh[2], bh[3]);
                mma16816(acc[1][2*f],     al1, bh[0], bh[1]);
                mma16816(acc[1][2*f + 1], al1, bh[2], bh[3]);
                ldsm4t(bl, WlB + boff);
                mma16816(acc[0][2*f],     ah0, bl[0], bl[1]);
                mma16816(acc[0][2*f + 1], ah0, bl[2], bl[3]);
                mma16816(acc[1][2*f],     ah1, bl[0], bl[1]);
                mma16816(acc[1][2*f + 1], ah1, bl[2], bl[3]);
            }
        }
    }
    __syncthreads();               // last mma done before epilogue overlays W region

    {
        const uint4* srcH = (const uint4*)(g_VhSwz + r*8192);
        const uint4* srcL = (const uint4*)(g_VlSwz + r*8192);
        #pragma unroll
        for (int q = 0; q < 4; q++) {
            ((uint4*)sh.u.e.Vh)[t + 128*q] = srcH[t + 128*q];
            ((uint4*)sh.u.e.Vl)[t + 128*q] = srcL[t + 128*q];
        }
    }

    float invn[2][2];
    #pragma unroll
    for (int T = 0; T < 2; T++) {
        float s0 = 0.f, s1 = 0.f;
        #pragma unroll
        for (int j = 0; j < 8; j++) {
            float b0 = sh.bs[8*j + 2*tq], b1 = sh.bs[8*j + 2*tq + 1];
            acc[T][j][0] += b0; acc[T][j][1] += b1;
            acc[T][j][2] += b0; acc[T][j][3] += b1;
            s0 += acc[T][j][0]*acc[T][j][0] + acc[T][j][1]*acc[T][j][1];
            s1 += acc[T][j][2]*acc[T][j][2] + acc[T][j][3]*acc[T][j][3];
        }
        s0 += __shfl_xor_sync(0xffffffffu, s0, 1);
        s0 += __shfl_xor_sync(0xffffffffu, s0, 2);
        s1 += __shfl_xor_sync(0xffffffffu, s1, 1);
        s1 += __shfl_xor_sync(0xffffffffu, s1, 2);
        invn[T][0] = 1.f / fmaxf(sqrtf(s0), 1e-12f);
        invn[T][1] = 1.f / fmaxf(sqrtf(s1), 1e-12f);
    }

    #pragma unroll
    for (int T = 0; T < 2; T++) {
        int rowA = R0 + 16*T + g, rowB = rowA + 8;
        uint32_t xorA = (uint32_t)(rowA & 7) << 4;
        uint32_t xorB = (uint32_t)(rowB & 7) << 4;
        #pragma unroll
        for (int j = 0; j < 8; j++) {
            uint32_t hp, lp;
            split2(acc[T][j][0]*invn[T][0], acc[T][j][1]*invn[T][0], hp, lp);
            uint32_t offA = ((uint32_t)rowA*128 + 16*j + 4*tq) ^ xorA;
            *(uint32_t*)(sh.u.e.Uh + offA) = hp;
            *(uint32_t*)(sh.u.e.Ul + offA) = lp;
            split2(acc[T][j][2]*invn[T][1], acc[T][j][3]*invn[T][1], hp, lp);
            uint32_t offB = ((uint32_t)rowB*128 + 16*j + 4*tq) ^ xorB;
            *(uint32_t*)(sh.u.e.Uh + offB) = hp;
            *(uint32_t*)(sh.u.e.Ul + offB) = lp;
        }
    }
    __syncthreads();

    uint32_t UhB = (uint32_t)__cvta_generic_to_shared(sh.u.e.Uh);
    uint32_t UlB = (uint32_t)__cvta_generic_to_shared(sh.u.e.Ul);
    uint32_t VhB = (uint32_t)__cvta_generic_to_shared(sh.u.e.Vh);
    uint32_t VlB = (uint32_t)__cvta_generic_to_shared(sh.u.e.Vl);
    #pragma unroll
    for (int T = 0; T < 2; T++)
        #pragma unroll
        for (int j = 0; j < 8; j++)
            #pragma unroll
            for (int q = 0; q < 4; q++) acc[T][j][q] = 0.f;
    #pragma unroll
    for (int kk = 0; kk < 4; kk++) {
        int arow = R0 + (lane & 15);
        uint32_t asel = (uint32_t)(2*kk + (lane >> 4))*16;
        uint32_t aoff0 = ((uint32_t)arow*128 + asel) ^ ((uint32_t)(arow & 7) << 4);
        int arow1 = arow + 16;
        uint32_t aoff1 = ((uint32_t)arow1*128 + asel) ^ ((uint32_t)(arow1 & 7) << 4);
        uint32_t ah0[4], al0[4], ah1[4], al1[4];
        ldsm4(ah0, UhB + aoff0); ldsm4(al0, UlB + aoff0);
        ldsm4(ah1, UhB + aoff1); ldsm4(al1, UlB + aoff1);
        int krow = 16*kk + (lane & 15);
        uint32_t bxor = (uint32_t)(krow & 7) << 4;
        #pragma unroll
        for (int f = 0; f < 4; f++) {
            uint32_t boff = ((uint32_t)krow*128 + (2*f + (lane >> 4))*16) ^ bxor;
            uint32_t bh[4], bl[4];
            ldsm4t(bh, VhB + boff);
            mma16816(acc[0][2*f],     ah0, bh[0], bh[1]);
            mma16816(acc[0][2*f + 1], ah0, bh[2], bh[3]);
            mma16816(acc[0][2*f],     al0, bh[0], bh[1]);
            mma16816(acc[0][2*f + 1], al0, bh[2], bh[3]);
            mma16816(acc[1][2*f],     ah1, bh[0], bh[1]);
            mma16816(acc[1][2*f + 1], ah1, bh[2], bh[3]);
            mma16816(acc[1][2*f],     al1, bh[0], bh[1]);
            mma16816(acc[1][2*f + 1], al1, bh[2], bh[3]);
            ldsm4t(bl, VlB + boff);
            mma16816(acc[0][2*f],     ah0, bl[0], bl[1]);
            mma16816(acc[0][2*f + 1], ah0, bl[2], bl[3]);
            mma16816(acc[1][2*f],     ah1, bl[0], bl[1]);
            mma16816(acc[1][2*f + 1], ah1, bl[2], bl[3]);
        }
    }

    #pragma unroll
    for (int T = 0; T < 2; T++) {
        float m0 = -1e30f, m1 = -1e30f;
        #pragma unroll
        for (int j = 0; j < 8; j++) {
            m0 = fmaxf(m0, fmaxf(acc[T][j][0], acc[T][j][1]));
            m1 = fmaxf(m1, fmaxf(acc[T][j][2], acc[T][j][3]));
        }
        m0 = fmaxf(m0, __shfl_xor_sync(0xffffffffu, m0, 1));
        m0 = fmaxf(m0, __shfl_xor_sync(0xffffffffu, m0, 2));
        m1 = fmaxf(m1, __shfl_xor_sync(0xffffffffu, m1, 1));
        m1 = fmaxf(m1, __shfl_xor_sync(0xffffffffu, m1, 2));
        float s0 = 0.f, s1 = 0.f;
        #pragma unroll
        for (int j = 0; j < 8; j++) {
            acc[T][j][0] = __expf(acc[T][j][0] - m0);
            acc[T][j][1] = __expf(acc[T][j][1] - m0);
            acc[T][j][2] = __expf(acc[T][j][2] - m1);
            acc[T][j][3] = __expf(acc[T][j][3] - m1);
            s0 += acc[T][j][0] + acc[T][j][1];
            s1 += acc[T][j][2] + acc[T][j][3];
        }
        s0 += __shfl_xor_sync(0xffffffffu, s0, 1);
        s0 += __shfl_xor_sync(0xffffffffu, s0, 2);
        s1 += __shfl_xor_sync(0xffffffffu, s1, 1);
        s1 += __shfl_xor_sync(0xffffffffu, s1, 2);
        int row0 = R0 + 16*T + g, row1 = row0 + 8;
        float sc0 = sh.gwv[row0] / s0;
        float sc1 = sh.gwv[row1] / s1;
        bool ok0 = (base + row0) < cnt;
        bool ok1 = (base + row1) < cnt;
        float* d0 = g_out + (size_t)sh.el[row0]*LSZ;
        float* d1 = g_out + (size_t)sh.el[row1]*LSZ;
        #pragma unroll
        for (int j = 0; j < 8; j++) {
            int col = 8*j + 2*tq;
            if (ok0) *(float2*)(d0 + col) = make_float2(acc[T][j][0]*sc0, acc[T][j][1]*sc0);
            if (ok1) *(float2*)(d1 + col) = make_float2(acc[T][j][2]*sc1, acc[T][j][3]*sc1);
        }
    }
}

// ---------------- sample (+aux): combine 2 entries, cumsum, pick, log -------------
__global__ __launch_bounds__(256) void sample_kernel(const float* __restrict__ rnd,
                                                     float* __restrict__ out_idx,
                                                     float* __restrict__ out_lp,
                                                     float* __restrict__ out_aux) {
    int t = threadIdx.x, lane = t & 31, w = t >> 5;
    if (blockIdx.x == 0 && t == 0) {
        float s = 0.f;
        #pragma unroll
        for (int r = 0; r < RSZ; r++)
            s += (g_probsum[r] / (float)NTOK) * ((float)g_cnt[r] / (float)NTOK);
        out_aux[0] = (float)RSZ * s * 0.05f;
    }
    int n = blockIdx.x*8 + w;
    const float* b = g_out + (size_t)2*n*LSZ;
    float v0 = b[lane]      + b[64 + lane];
    float v1 = b[32 + lane] + b[96 + lane];
    float rv = rnd[n];
    float s0 = v0;
    #pragma unroll
    for (int o = 1; o < 32; o <<= 1) {
        float u = __shfl_up_sync(0xffffffffu, s0, o);
        if (lane >= o) s0 += u;
    }
    float tot0 = __shfl_sync(0xffffffffu, s0, 31);
    float s1 = v1;
    #pragma unroll
    for (int o = 1; o < 32; o <<= 1) {
        float u = __shfl_up_sync(0xffffffffu, s1, o);
        if (lane >= o) s1 += u;
    }
    s1 += tot0;
    unsigned b0 = __ballot_sync(0xffffffffu, s0 > rv);
    unsigned b1 = __ballot_sync(0xffffffffu, s1 > rv);
    int sel = b0 ? (__ffs(b0) - 1) : (b1 ? (31 + __ffs(b1)) : 0);
    float p = (sel < 32) ? __shfl_sync(0xffffffffu, v0, sel)
                         : __shfl_sync(0xffffffffu, v1, sel - 32);
    if (lane == 0) {
        out_idx[n] = (float)sel;
        out_lp[n]  = logf(p);
    }
}

// ---------------- launch ----------------
extern "C" void kernel_launch(void* const* d_in, const int* in_sizes, int n_in,
                              void* d_out, int out_size) {
    const float* posts = (const float*)d_in[0];
    const float* reas  = (const float*)d_in[1];
    const float* llm   = (const float*)d_in[2];
    const float* rnd   = (const float*)d_in[3];
    const float* gw    = (const float*)d_in[4];
    const float* gb    = (const float*)d_in[5];
    const float* Uw    = (const float*)d_in[6];
    const float* Ub    = (const float*)d_in[7];
    const float* Vw    = (const float*)d_in[8];
    const float* Vb    = (const float*)d_in[9];
    float* out = (float*)d_out;

    static bool attr_done = false;
    if (!attr_done) {
        cudaFuncSetAttribute(proj_kernel, cudaFuncAttributeMaxDynamicSharedMemorySize,
                             (int)sizeof(ProjSmem));
        cudaFuncSetAttribute(gate_kernel, cudaFuncAttributeMaxDynamicSharedMemorySize,
                             (int)sizeof(GateSmem));
        attr_done = true;
    }

    wsplit_kernel<<<RSZ*12, 128>>>(Uw);
    vl_kernel<<<dim3(LSZ, RSZ), 64>>>(llm, Vw, Vb);
    gate_kernel<<<NTOK/GB, 256, sizeof(GateSmem)>>>(posts, reas, gw, gb);
    proj_kernel<<<dim3(NTOK/128, RSZ), 128, sizeof(ProjSmem)>>>(posts, reas, Ub);
    sample_kernel<<<NTOK/8, 256>>>(rnd, out, out + NTOK, out + 2*NTOK);
}

// round 14
// speedup vs baseline: 1.1322x; 1.1322x over previous
#include <cuda_runtime.h>
#include <cuda_bf16.h>
#include <math.h>
#include <stdint.h>

#define NTOK  65536
#define DHALF 384
#define DFULL 768
#define LSZ   64
#define HSZ   64
#define RSZ   8

// ---------------- device scratch (static; no allocations) ----------------
__device__ int   g_cnt[RSZ];
__device__ float g_probsum[RSZ];
__device__ int   g_list[RSZ*NTOK];              // entry e = 2*n + slot
__device__ float g_gate[2*NTOK];                // gate weight per entry
__device__ float g_out[(size_t)2*NTOK*LSZ];     // gate-scaled softmax scores per entry
// pre-split, pre-swizzled Vl (ldmatrix layout, [r] blocks of 64 rows x 128B)
__device__ __align__(16) char g_VhSwz[RSZ*8192];
__device__ __align__(16) char g_VlSwz[RSZ*8192];
// pre-split, pre-swizzled U_w: [r][chunk c<12] blocks of 64 k-rows x 128B
__device__ __align__(16) char g_Wh[RSZ*12*8192];
__device__ __align__(16) char g_Wl[RSZ*12*8192];

// ---------------- helpers ----------------
__device__ __forceinline__ uint32_t packbf(float lo, float hi) {
    uint32_t d;
    asm("cvt.rn.bf16x2.f32 %0, %1, %2;" : "=r"(d) : "f"(hi), "f"(lo));
    return d;
}
__device__ __forceinline__ void split2(float x0, float x1, uint32_t& hp, uint32_t& lp) {
    hp = packbf(x0, x1);
    float h0 = __uint_as_float(hp << 16);
    float h1 = __uint_as_float(hp & 0xffff0000u);
    lp = packbf(x0 - h0, x1 - h1);
}
__device__ __forceinline__ void ldsm4(uint32_t r[4], uint32_t addr) {
    asm volatile("ldmatrix.sync.aligned.m8n8.x4.shared.b16 {%0,%1,%2,%3}, [%4];"
        : "=r"(r[0]), "=r"(r[1]), "=r"(r[2]), "=r"(r[3]) : "r"(addr));
}
__device__ __forceinline__ void ldsm4t(uint32_t r[4], uint32_t addr) {
    asm volatile("ldmatrix.sync.aligned.m8n8.x4.trans.shared.b16 {%0,%1,%2,%3}, [%4];"
        : "=r"(r[0]), "=r"(r[1]), "=r"(r[2]), "=r"(r[3]) : "r"(addr));
}
__device__ __forceinline__ void mma16816(float c[4], const uint32_t a[4],
                                         uint32_t b0, uint32_t b1) {
    asm volatile("mma.sync.aligned.m16n8k16.row.col.f32.bf16.bf16.f32 "
        "{%0,%1,%2,%3}, {%4,%5,%6,%7}, {%8,%9}, {%0,%1,%2,%3};"
        : "+f"(c[0]), "+f"(c[1]), "+f"(c[2]), "+f"(c[3])
        : "r"(a[0]), "r"(a[1]), "r"(a[2]), "r"(a[3]), "r"(b0), "r"(b1));
}
__device__ __forceinline__ void cp16(uint32_t dst, const void* src) {
    asm volatile("cp.async.ca.shared.global [%0], [%1], 16;" :: "r"(dst), "l"(src));
}

// ---------------- W presplit (+init): U_w -> bf16 hi/lo, swizzled ----------
__global__ __launch_bounds__(128) void wsplit_kernel(const float* __restrict__ Uw) {
    int bx = blockIdx.x;
    int r = bx / 12, c = bx % 12;
    int t = threadIdx.x;
    if (bx == 0 && t < RSZ) { g_cnt[t] = 0; g_probsum[t] = 0.f; }
    int wrow = t >> 1, whalf = t & 1;
    const float* src = Uw + ((size_t)r*DFULL + c*64 + wrow)*HSZ + whalf*32;
    char* dh = g_Wh + ((size_t)(r*12 + c))*8192;
    char* dl = g_Wl + ((size_t)(r*12 + c))*8192;
    uint32_t rowb = (uint32_t)(wrow*128 + whalf*64);
    uint32_t xorv = (uint32_t)(wrow & 7) << 4;
    #pragma unroll
    for (int q2 = 0; q2 < 4; q2++) {
        float4 v0 = ((const float4*)src)[2*q2];
        float4 v1 = ((const float4*)src)[2*q2 + 1];
        uint32_t h0,h1,h2,h3,l0,l1,l2,l3;
        split2(v0.x, v0.y, h0, l0); split2(v0.z, v0.w, h1, l1);
        split2(v1.x, v1.y, h2, l2); split2(v1.z, v1.w, h3, l3);
        uint32_t off = (rowb + q2*16) ^ xorv;
        *(uint4*)(dh + off) = make_uint4(h0,h1,h2,h3);
        *(uint4*)(dl + off) = make_uint4(l0,l1,l2,l3);
    }
}

// ---------------- Vl = l2norm(llm @ V_w[r] + V_b[r]); emit swizzled bf16 hi/lo -------
__global__ __launch_bounds__(64) void vl_kernel(const float* __restrict__ llm,
                                                const float* __restrict__ Vw,
                                                const float* __restrict__ Vb) {
    int l = blockIdx.x, r = blockIdx.y, h = threadIdx.x;
    __shared__ float lsm[DHALF];
    __shared__ float red[64];
    __shared__ float s_inv;
    for (int i = h; i < DHALF; i += 64) lsm[i] = llm[l*DHALF + i];
    __syncthreads();
    float acc = Vb[r*HSZ + h];
    const float* w = Vw + ((size_t)r*DHALF)*HSZ + h;
    #pragma unroll 8
    for (int d = 0; d < DHALF; d++) acc += lsm[d] * w[(size_t)d*HSZ];
    red[h] = acc*acc;
    __syncthreads();
    if (h == 0) {
        float ss = 0.f;
        #pragma unroll
        for (int i = 0; i < 64; i++) ss += red[i];
        s_inv = 1.f / fmaxf(sqrtf(ss), 1e-12f);
    }
    __syncthreads();
    float val = acc * s_inv;
    unsigned short hbits = __bfloat16_as_ushort(__float2bfloat16(val));
    float hf = __uint_as_float(((uint32_t)hbits) << 16);
    unsigned short lbits = __bfloat16_as_ushort(__float2bfloat16(val - hf));
    uint32_t off = (uint32_t)(h*128 + l*2) ^ ((uint32_t)(h & 7) << 4);
    *(unsigned short*)(g_VhSwz + r*8192 + off) = hbits;
    *(unsigned short*)(g_VlSwz + r*8192 + off) = lbits;
}

// ---------------- gate v5: lane = token; broadcast w; cp.async double buffer -------
#define GB 256
struct GateSmem {
    float Wt[RSZ][772];        // [r][k], warp-uniform reads (broadcast)
    float Xc[2][8][32][36];    // double-buffered per-warp x chunk (32 floats + pad)
    float pblk[8][RSZ];
    float bsm[RSZ];
    int   i1s[GB], i2s[GB];
    int   locs[2*GB];
    int   cnt2[16];
    int   bases[RSZ];
};

__global__ __launch_bounds__(256, 2) void gate_kernel(const float* __restrict__ posts,
                                                      const float* __restrict__ reas,
                                                      const float* __restrict__ gw,
                                                      const float* __restrict__ gb) {
    extern __shared__ char gsraw[];
    GateSmem& sh = *reinterpret_cast<GateSmem*>(gsraw);
    int t = threadIdx.x, lane = t & 31, w = t >> 5;
    int nblk = blockIdx.x * GB;
    int n = nblk + t;                       // this lane's token

    for (int i = t; i < DFULL*RSZ; i += 256) {
        int k = i >> 3, rr = i & 7;
        sh.Wt[rr][k] = gw[i];
    }
    if (t < RSZ) sh.bsm[t] = gb[t];

    uint32_t XcB = (uint32_t)__cvta_generic_to_shared(&sh.Xc[0][0][0][0]);
    int tokb = lane >> 3, fq = lane & 7;    // staging: 4 tokens x 8 float4 per phase

    auto stage = [&](int c, int buf) {
        const float* bsrc = (c < 12) ? posts : reas;
        int off = (c < 12) ? c*32 : (c - 12)*32;
        #pragma unroll
        for (int ii = 0; ii < 8; ii++) {
            int tok = ii*4 + tokb;
            const float* src = bsrc + (size_t)(nblk + w*32 + tok)*DHALF + off + 4*fq;
            uint32_t dst = XcB + (uint32_t)(((buf*8 + w)*32 + tok)*144 + 16*fq);
            cp16(dst, src);
        }
        asm volatile("cp.async.commit_group;" ::: "memory");
    };

    float acc[RSZ];
    #pragma unroll
    for (int r = 0; r < RSZ; r++) acc[r] = 0.f;

    stage(0, 0);
    __syncthreads();   // Wt/bsm ready (staging itself is warp-local via cp.async)

    for (int c = 0; c < 24; c++) {
        if (c + 1 < 24) {
            stage(c + 1, (c + 1) & 1);
            asm volatile("cp.async.wait_group 1;" ::: "memory");
        } else {
            asm volatile("cp.async.wait_group 0;" ::: "memory");
        }
        __syncwarp();
        int buf = c & 1;
        #pragma unroll
        for (int j4 = 0; j4 < 8; j4++) {
            float4 xv = *(const float4*)&sh.Xc[buf][w][lane][4*j4];
            #pragma unroll
            for (int r = 0; r < RSZ; r++) {
                float4 wv = *(const float4*)&sh.Wt[r][c*32 + 4*j4];
                acc[r] += xv.x*wv.x + xv.y*wv.y + xv.z*wv.z + xv.w*wv.w;
            }
        }
        __syncwarp();
    }

    float lg[RSZ];
    #pragma unroll
    for (int r = 0; r < RSZ; r++) lg[r] = acc[r] + sh.bsm[r];

    // serial top-2 (strict >, earlier index wins ties — matches jax top_k)
    float v1 = -1e30f, v2 = -1e30f; int i1 = 0, i2 = 0;
    #pragma unroll
    for (int r = 0; r < RSZ; r++) {
        if (lg[r] > v1)      { v2 = v1; i2 = i1; v1 = lg[r]; i1 = r; }
        else if (lg[r] > v2) { v2 = lg[r]; i2 = r; }
    }
    // softmax over 8 routers (aux probsum)
    float p[RSZ], s = 0.f;
    #pragma unroll
    for (int r = 0; r < RSZ; r++) { p[r] = expf(lg[r] - v1); s += p[r]; }
    float invs = 1.f / s;
    #pragma unroll
    for (int r = 0; r < RSZ; r++) {
        float q = p[r] * invs;
        q += __shfl_xor_sync(0xffffffffu, q, 16);
        q += __shfl_xor_sync(0xffffffffu, q, 8);
        q += __shfl_xor_sync(0xffffffffu, q, 4);
        q += __shfl_xor_sync(0xffffffffu, q, 2);
        q += __shfl_xor_sync(0xffffffffu, q, 1);
        if (lane == 0) sh.pblk[w][r] = q;
    }
    float g0 = 1.f / (1.f + expf(v2 - v1));
    g_gate[2*n]   = g0;
    g_gate[2*n+1] = 1.f - g0;
    sh.i1s[t] = i1; sh.i2s[t] = i2;
    __syncthreads();

    // stable compaction, 16 scanners (r, half)
    if (t < 16) {
        int r = t & 7, h = t >> 3;
        int c = 0;
        for (int e = h*GB; e < (h + 1)*GB; e++) {
            int rid = (e & 1) ? sh.i2s[e >> 1] : sh.i1s[e >> 1];
            if (rid == r) sh.locs[e] = c++;
        }
        sh.cnt2[t] = c;
    }
    __syncthreads();
    if (t < RSZ) sh.bases[t] = atomicAdd(&g_cnt[t], sh.cnt2[t] + sh.cnt2[t + 8]);
    __syncthreads();
    #pragma unroll
    for (int pass = 0; pass < 2; pass++) {
        int e = t + pass*256;
        int rid = (e & 1) ? sh.i2s[e >> 1] : sh.i1s[e >> 1];
        int off = sh.bases[rid] + sh.locs[e] + ((e >= GB) ? sh.cnt2[rid] : 0);
        g_list[rid*NTOK + off] = 2*(nblk + (e >> 1)) + (e & 1);
    }
    if (t < RSZ) {
        float sm = 0.f;
        #pragma unroll
        for (int wi = 0; wi < 8; wi++) sm += sh.pblk[wi][t];
        atomicAdd(&g_probsum[t], sm);
    }
}

// ---------------- proj: bf16x3 tensor MMA, W double-buffer + half X prefetch ------
struct ProjSmem {
    union {
        struct { char Ah[16384]; char Al[16384];
                 char Wh[2][8192]; char Wl[2][8192]; } m;   // 64 KB
        struct { char Uh[16384]; char Ul[16384]; char Vh[8192]; char Vl[8192]; } e;
    } u;
    int   el[128];
    float gwv[128];
    float bs[64];
};

__global__ __launch_bounds__(128, 3) void proj_kernel(const float* __restrict__ posts,
                                                      const float* __restrict__ reas,
                                                      const float* __restrict__ Ub) {
    int r = blockIdx.y;
    int cnt = g_cnt[r];
    int base = blockIdx.x * 128;
    if (base >= cnt) return;

    extern __shared__ char smraw[];
    ProjSmem& sh = *reinterpret_cast<ProjSmem*>(smraw);

    int t = threadIdx.x, lane = t & 31, w = t >> 5;
    const int R0 = 32*w;
    const int g  = lane >> 2;
    const int tq = lane & 3;

    {
        int i = base + t;
        int e = (i < cnt) ? g_list[r*NTOK + i] : g_list[r*NTOK + base];
        sh.el[t] = e;
        sh.gwv[t] = g_gate[e];
    }
    if (t < 64) sh.bs[t] = Ub[r*HSZ + t];
    __syncthreads();

    uint32_t AhB = (uint32_t)__cvta_generic_to_shared(sh.u.m.Ah);
    uint32_t AlB = (uint32_t)__cvta_generic_to_shared(sh.u.m.Al);
    uint32_t WhB = (uint32_t)__cvta_generic_to_shared(&sh.u.m.Wh[0][0]);
    uint32_t WlB = (uint32_t)__cvta_generic_to_shared(&sh.u.m.Wl[0][0]);

    const int half = lane >> 4, fq = lane & 15;

    auto srcPtr = [&](int c, int row) {
        const float* bsrc = (c < 6) ? posts : reas;
        int off_in = (c < 6) ? c*64 : (c - 6)*64;
        return bsrc + (size_t)(sh.el[row] >> 1)*DHALF + off_in;
    };
    auto stSwz = [&](int row, float4 v) {
        uint32_t hp, lp, hp2, lp2;
        split2(v.x, v.y, hp, lp);
        split2(v.z, v.w, hp2, lp2);
        uint32_t off = ((uint32_t)row*128 + fq*8) ^ ((uint32_t)(row & 7) << 4);
        *(uint2*)(sh.u.m.Ah + off) = make_uint2(hp, hp2);
        *(uint2*)(sh.u.m.Al + off) = make_uint2(lp, lp2);
    };
    auto stW = [&](int c) {
        int buf = c & 1;
        const char* srcH = g_Wh + ((size_t)(r*12 + c))*8192 + t*64;
        const char* srcL = g_Wl + ((size_t)(r*12 + c))*8192 + t*64;
        uint32_t dH = WhB + (uint32_t)buf*8192 + t*64;
        uint32_t dL = WlB + (uint32_t)buf*8192 + t*64;
        #pragma unroll
        for (int q = 0; q < 4; q++) {
            cp16(dH + 16*q, srcH + 16*q);
            cp16(dL + 16*q, srcL + 16*q);
        }
        asm volatile("cp.async.commit_group;" ::: "memory");
    };

    float4 xpre[8];
    auto ldFirst = [&](int c) {
        #pragma unroll
        for (int i = 0; i < 8; i++) {
            int row = 32*w + 2*i + half;
            xpre[i] = ((const float4*)srcPtr(c, row))[fq];
        }
    };

    float acc[2][8][4];
    #pragma unroll
    for (int T = 0; T < 2; T++)
        #pragma unroll
        for (int j = 0; j < 8; j++)
            #pragma unroll
            for (int q = 0; q < 4; q++) acc[T][j][q] = 0.f;

    ldFirst(0);
    stW(0);

    for (int c = 0; c < 12; c++) {
        // ---- stage X: first 8 pairs from prefetch regs, last 8 fresh ----
        #pragma unroll
        for (int i = 0; i < 8; i++) {
            int row = 32*w + 2*i + half;
            stSwz(row, xpre[i]);
        }
        #pragma unroll
        for (int i = 8; i < 16; i++) {
            int row = 32*w + 2*i + half;
            float4 v = ((const float4*)srcPtr(c, row))[fq];
            stSwz(row, v);
        }
        if (c + 1 < 12) {
            stW(c + 1);
            ldFirst(c + 1);
            asm volatile("cp.async.wait_group 1;" ::: "memory");
        } else {
            asm volatile("cp.async.wait_group 0;" ::: "memory");
        }
        __syncthreads();
        // ---- tensor mainloop: 4 k16-steps, bf16x3, B shared across 2 m-tiles ----
        uint32_t wbuf = (uint32_t)(c & 1) * 8192;
        #pragma unroll
        for (int kk = 0; kk < 4; kk++) {
            int arow = R0 + (lane & 15);
            uint32_t asel = (uint32_t)(2*kk + (lane >> 4))*16;
            uint32_t aoff0 = ((uint32_t)arow*128 + asel) ^ ((uint32_t)(arow & 7) << 4);
            int arow1 = arow + 16;
            uint32_t aoff1 = ((uint32_t)arow1*128 + asel) ^ ((uint32_t)(arow1 & 7) << 4);
            uint32_t ah0[4], al0[4], ah1[4], al1[4];
            ldsm4(ah0, AhB + aoff0); ldsm4(al0, AlB + aoff0);
            ldsm4(ah1, AhB + aoff1); ldsm4(al1, AlB + aoff1);
            int krow = 16*kk + (lane & 15);
            uint32_t bxor = (uint32_t)(krow & 7) << 4;
            #pragma unroll
            for (int f = 0; f < 4; f++) {
                uint32_t boff = (((uint32_t)krow*128 + (2*f + (lane >> 4))*16) ^ bxor) + wbuf;
                uint32_t bh[4], bl[4];
                ldsm4t(bh, WhB + boff);
                mma16816(acc[0][2*f],     ah0, bh[0], bh[1]);
                mma16816(acc[0][2*f + 1], ah0, bh[2], bh[3]);
                mma16816(acc[0][2*f],     al0, bh[0], bh[1]);
                mma16816(acc[0][2*f + 1], al0, bh[2], bh[3]);
                mma16816(acc[1][2*f],     ah1, bh[0], bh[1]);
                mma16816(acc[1][2*f + 1], ah1, bh[2], bh[3]);
                mma16816(acc[1][2*f],     al1, bh[0], bh[1]);
                mma16816(acc[1][2*f + 1], al1, bh[2], bh[3]);
                ldsm4t(bl, WlB + boff);
                mma16816(acc[0][2*f],     ah0, bl[0], bl[1]);
                mma16816(acc[0][2*f + 1], ah0, bl[2], bl[3]);
                mma16816(acc[1][2*f],     ah1, bl[0], bl[1]);
                mma16816(acc[1][2*f + 1], ah1, bl[2], bl[3]);
            }
        }
        __syncthreads();
    }

    // ---- copy pre-swizzled V tiles (overlays W region; mainloop done) ----
    {
        const uint4* srcH = (const uint4*)(g_VhSwz + r*8192);
        const uint4* srcL = (const uint4*)(g_VlSwz + r*8192);
        #pragma unroll
        for (int q = 0; q < 4; q++) {
            ((uint4*)sh.u.e.Vh)[t + 128*q] = srcH[t + 128*q];
            ((uint4*)sh.u.e.Vl)[t + 128*q] = srcL[t + 128*q];
        }
    }

    float invn[2][2];
    #pragma unroll
    for (int T = 0; T < 2; T++) {
        float s0 = 0.f, s1 = 0.f;
        #pragma unroll
        for (int j = 0; j < 8; j++) {
            float b0 = sh.bs[8*j + 2*tq], b1 = sh.bs[8*j + 2*tq + 1];
            acc[T][j][0] += b0; acc[T][j][1] += b1;
            acc[T][j][2] += b0; acc[T][j][3] += b1;
            s0 += acc[T][j][0]*acc[T][j][0] + acc[T][j][1]*acc[T][j][1];
            s1 += acc[T][j][2]*acc[T][j][2] + acc[T][j][3]*acc[T][j][3];
        }
        s0 += __shfl_xor_sync(0xffffffffu, s0, 1);
        s0 += __shfl_xor_sync(0xffffffffu, s0, 2);
        s1 += __shfl_xor_sync(0xffffffffu, s1, 1);
        s1 += __shfl_xor_sync(0xffffffffu, s1, 2);
        invn[T][0] = 1.f / fmaxf(sqrtf(s0), 1e-12f);
        invn[T][1] = 1.f / fmaxf(sqrtf(s1), 1e-12f);
    }

    #pragma unroll
    for (int T = 0; T < 2; T++) {
        int rowA = R0 + 16*T + g, rowB = rowA + 8;
        uint32_t xorA = (uint32_t)(rowA & 7) << 4;
        uint32_t xorB = (uint32_t)(rowB & 7) << 4;
        #pragma unroll
        for (int j = 0; j < 8; j++) {
            uint32_t hp, lp;
            split2(acc[T][j][0]*invn[T][0], acc[T][j][1]*invn[T][0], hp, lp);
            uint32_t offA = ((uint32_t)rowA*128 + 16*j + 4*tq) ^ xorA;
            *(uint32_t*)(sh.u.e.Uh + offA) = hp;
            *(uint32_t*)(sh.u.e.Ul + offA) = lp;
            split2(acc[T][j][2]*invn[T][1], acc[T][j][3]*invn[T][1], hp, lp);
            uint32_t offB = ((uint32_t)rowB*128 + 16*j + 4*tq) ^ xorB;
            *(uint32_t*)(sh.u.e.Uh + offB) = hp;
            *(uint32_t*)(sh.u.e.Ul + offB) = lp;
        }
    }
    __syncthreads();

    uint32_t UhB = (uint32_t)__cvta_generic_to_shared(sh.u.e.Uh);
    uint32_t UlB = (uint32_t)__cvta_generic_to_shared(sh.u.e.Ul);
    uint32_t VhB = (uint32_t)__cvta_generic_to_shared(sh.u.e.Vh);
    uint32_t VlB = (uint32_t)__cvta_generic_to_shared(sh.u.e.Vl);
    #pragma unroll
    for (int T = 0; T < 2; T++)
        #pragma unroll
        for (int j = 0; j < 8; j++)
            #pragma unroll
            for (int q = 0; q < 4; q++) acc[T][j][q] = 0.f;
    #pragma unroll
    for (int kk = 0; kk < 4; kk++) {
        int arow = R0 + (lane & 15);
        uint32_t asel = (uint32_t)(2*kk + (lane >> 4))*16;
        uint32_t aoff0 = ((uint32_t)arow*128 + asel) ^ ((uint32_t)(arow & 7) << 4);
        int arow1 = arow + 16;
        uint32_t aoff1 = ((uint32_t)arow1*128 + asel) ^ ((uint32_t)(arow1 & 7) << 4);
        uint32_t ah0[4], al0[4], ah1[4], al1[4];
        ldsm4(ah0, UhB + aoff0); ldsm4(al0, UlB + aoff0);
        ldsm4(ah1, UhB + aoff1); ldsm4(al1, UlB + aoff1);
        int krow = 16*kk + (lane & 15);
        uint32_t bxor = (uint32_t)(krow & 7) << 4;
        #pragma unroll
        for (int f = 0; f < 4; f++) {
            uint32_t boff = ((uint32_t)krow*128 + (2*f + (lane >> 4))*16) ^ bxor;
            uint32_t bh[4], bl[4];
            ldsm4t(bh, VhB + boff);
            mma16816(acc[0][2*f],     ah0, bh[0], bh[1]);
            mma16816(acc[0][2*f + 1], ah0, bh[2], bh[3]);
            mma16816(acc[0][2*f],     al0, bh[0], bh[1]);
            mma16816(acc[0][2*f + 1], al0, bh[2], bh[3]);
            mma16816(acc[1][2*f],     ah1, bh[0], bh[1]);
            mma16816(acc[1][2*f + 1], ah1, bh[2], bh[3]);
            mma16816(acc[1][2*f],     al1, bh[0], bh[1]);
            mma16816(acc[1][2*f + 1], al1, bh[2], bh[3]);
            ldsm4t(bl, VlB + boff);
            mma16816(acc[0][2*f],     ah0, bl[0], bl[1]);
            mma16816(acc[0][2*f + 1], ah0, bl[2], bl[3]);
            mma16816(acc[1][2*f],     ah1, bl[0], bl[1]);
            mma16816(acc[1][2*f + 1], ah1, bl[2], bl[3]);
        }
    }

    #pragma unroll
    for (int T = 0; T < 2; T++) {
        float m0 = -1e30f, m1 = -1e30f;
        #pragma unroll
        for (int j = 0; j < 8; j++) {
            m0 = fmaxf(m0, fmaxf(acc[T][j][0], acc[T][j][1]));
            m1 = fmaxf(m1, fmaxf(acc[T][j][2], acc[T][j][3]));
        }
        m0 = fmaxf(m0, __shfl_xor_sync(0xffffffffu, m0, 1));
        m0 = fmaxf(m0, __shfl_xor_sync(0xffffffffu, m0, 2));
        m1 = fmaxf(m1, __shfl_xor_sync(0xffffffffu, m1, 1));
        m1 = fmaxf(m1, __shfl_xor_sync(0xffffffffu, m1, 2));
        float s0 = 0.f, s1 = 0.f;
        #pragma unroll
        for (int j = 0; j < 8; j++) {
            acc[T][j][0] = __expf(acc[T][j][0] - m0);
            acc[T][j][1] = __expf(acc[T][j][1] - m0);
            acc[T][j][2] = __expf(acc[T][j][2] - m1);
            acc[T][j][3] = __expf(acc[T][j][3] - m1);
            s0 += acc[T][j][0] + acc[T][j][1];
            s1 += acc[T][j][2] + acc[T][j][3];
        }
        s0 += __shfl_xor_sync(0xffffffffu, s0, 1);
        s0 += __shfl_xor_sync(0xffffffffu, s0, 2);
        s1 += __shfl_xor_sync(0xffffffffu, s1, 1);
        s1 += __shfl_xor_sync(0xffffffffu, s1, 2);
        int row0 = R0 + 16*T + g, row1 = row0 + 8;
        float sc0 = sh.gwv[row0] / s0;
        float sc1 = sh.gwv[row1] / s1;
        bool ok0 = (base + row0) < cnt;
        bool ok1 = (base + row1) < cnt;
        float* d0 = g_out + (size_t)sh.el[row0]*LSZ;
        float* d1 = g_out + (size_t)sh.el[row1]*LSZ;
        #pragma unroll
        for (int j = 0; j < 8; j++) {
            int col = 8*j + 2*tq;
            if (ok0) *(float2*)(d0 + col) = make_float2(acc[T][j][0]*sc0, acc[T][j][1]*sc0);
            if (ok1) *(float2*)(d1 + col) = make_float2(acc[T][j][2]*sc1, acc[T][j][3]*sc1);
        }
    }
}

// ---------------- sample (+aux): combine 2 entries, cumsum, pick, log -------------
__global__ __launch_bounds__(256) void sample_kernel(const float* __restrict__ rnd,
                                                     float* __restrict__ out_idx,
                                                     float* __restrict__ out_lp,
                                                     float* __restrict__ out_aux) {
    int t = threadIdx.x, lane = t & 31, w = t >> 5;
    if (blockIdx.x == 0 && t == 0) {
        float s = 0.f;
        #pragma unroll
        for (int r = 0; r < RSZ; r++)
            s += (g_probsum[r] / (float)NTOK) * ((float)g_cnt[r] / (float)NTOK);
        out_aux[0] = (float)RSZ * s * 0.05f;
    }
    int n = blockIdx.x*8 + w;
    const float* b = g_out + (size_t)2*n*LSZ;
    float v0 = b[lane]      + b[64 + lane];
    float v1 = b[32 + lane] + b[96 + lane];
    float rv = rnd[n];
    float s0 = v0;
    #pragma unroll
    for (int o = 1; o < 32; o <<= 1) {
        float u = __shfl_up_sync(0xffffffffu, s0, o);
        if (lane >= o) s0 += u;
    }
    float tot0 = __shfl_sync(0xffffffffu, s0, 31);
    float s1 = v1;
    #pragma unroll
    for (int o = 1; o < 32; o <<= 1) {
        float u = __shfl_up_sync(0xffffffffu, s1, o);
        if (lane >= o) s1 += u;
    }
    s1 += tot0;
    unsigned b0 = __ballot_sync(0xffffffffu, s0 > rv);
    unsigned b1 = __ballot_sync(0xffffffffu, s1 > rv);
    int sel = b0 ? (__ffs(b0) - 1) : (b1 ? (31 + __ffs(b1)) : 0);
    float p = (sel < 32) ? __shfl_sync(0xffffffffu, v0, sel)
                         : __shfl_sync(0xffffffffu, v1, sel - 32);
    if (lane == 0) {
        out_idx[n] = (float)sel;
        out_lp[n]  = logf(p);
    }
}

// ---------------- launch ----------------
extern "C" void kernel_launch(void* const* d_in, const int* in_sizes, int n_in,
                              void* d_out, int out_size) {
    const float* posts = (const float*)d_in[0];
    const float* reas  = (const float*)d_in[1];
    const float* llm   = (const float*)d_in[2];
    const float* rnd   = (const float*)d_in[3];
    const float* gw    = (const float*)d_in[4];
    const float* gb    = (const float*)d_in[5];
    const float* Uw    = (const float*)d_in[6];
    const float* Ub    = (const float*)d_in[7];
    const float* Vw    = (const float*)d_in[8];
    const float* Vb    = (const float*)d_in[9];
    float* out = (float*)d_out;

    static bool attr_done = false;
    if (!attr_done) {
        cudaFuncSetAttribute(proj_kernel, cudaFuncAttributeMaxDynamicSharedMemorySize,
                             (int)sizeof(ProjSmem));
        cudaFuncSetAttribute(gate_kernel, cudaFuncAttributeMaxDynamicSharedMemorySize,
                             (int)sizeof(GateSmem));
        attr_done = true;
    }

    wsplit_kernel<<<RSZ*12, 128>>>(Uw);
    vl_kernel<<<dim3(LSZ, RSZ), 64>>>(llm, Vw, Vb);
    gate_kernel<<<NTOK/GB, 256, sizeof(GateSmem)>>>(posts, reas, gw, gb);
    proj_kernel<<<dim3(NTOK/128, RSZ), 128, sizeof(ProjSmem)>>>(posts, reas, Ub);
    sample_kernel<<<NTOK/8, 256>>>(rnd, out, out + NTOK, out + 2*NTOK);
}

// round 15
// speedup vs baseline: 1.8239x; 1.6110x over previous
#include <cuda_runtime.h>
#include <cuda_bf16.h>
#include <math.h>
#include <stdint.h>

#define NTOK  65536
#define DHALF 384
#define DFULL 768
#define LSZ   64
#define HSZ   64
#define RSZ   8

// ---------------- device scratch (static; no allocations) ----------------
__device__ int   g_cnt[RSZ];
__device__ float g_probsum[RSZ];
__device__ int   g_list[RSZ*NTOK];              // entry e = 2*n + slot
__device__ float g_gate[2*NTOK];                // gate weight per entry
__device__ float g_out[(size_t)2*NTOK*LSZ];     // gate-scaled softmax scores per entry
// pre-split, pre-swizzled Vl (ldmatrix layout, [r] blocks of 64 rows x 128B)
__device__ __align__(16) char g_VhSwz[RSZ*8192];
__device__ __align__(16) char g_VlSwz[RSZ*8192];
// pre-split, pre-swizzled U_w: [r][chunk c<12] blocks of 64 k-rows x 128B
__device__ __align__(16) char g_Wh[RSZ*12*8192];
__device__ __align__(16) char g_Wl[RSZ*12*8192];

// ---------------- helpers ----------------
__device__ __forceinline__ uint32_t packbf(float lo, float hi) {
    uint32_t d;
    asm("cvt.rn.bf16x2.f32 %0, %1, %2;" : "=r"(d) : "f"(hi), "f"(lo));
    return d;
}
__device__ __forceinline__ void split2(float x0, float x1, uint32_t& hp, uint32_t& lp) {
    hp = packbf(x0, x1);
    float h0 = __uint_as_float(hp << 16);
    float h1 = __uint_as_float(hp & 0xffff0000u);
    lp = packbf(x0 - h0, x1 - h1);
}
__device__ __forceinline__ void ldsm4(uint32_t r[4], uint32_t addr) {
    asm volatile("ldmatrix.sync.aligned.m8n8.x4.shared.b16 {%0,%1,%2,%3}, [%4];"
        : "=r"(r[0]), "=r"(r[1]), "=r"(r[2]), "=r"(r[3]) : "r"(addr));
}
__device__ __forceinline__ void ldsm4t(uint32_t r[4], uint32_t addr) {
    asm volatile("ldmatrix.sync.aligned.m8n8.x4.trans.shared.b16 {%0,%1,%2,%3}, [%4];"
        : "=r"(r[0]), "=r"(r[1]), "=r"(r[2]), "=r"(r[3]) : "r"(addr));
}
__device__ __forceinline__ void mma16816(float c[4], const uint32_t a[4],
                                         uint32_t b0, uint32_t b1) {
    asm volatile("mma.sync.aligned.m16n8k16.row.col.f32.bf16.bf16.f32 "
        "{%0,%1,%2,%3}, {%4,%5,%6,%7}, {%8,%9}, {%0,%1,%2,%3};"
        : "+f"(c[0]), "+f"(c[1]), "+f"(c[2]), "+f"(c[3])
        : "r"(a[0]), "r"(a[1]), "r"(a[2]), "r"(a[3]), "r"(b0), "r"(b1));
}
__device__ __forceinline__ void cp16(uint32_t dst, const void* src) {
    asm volatile("cp.async.ca.shared.global [%0], [%1], 16;" :: "r"(dst), "l"(src));
}

// ---------------- W presplit (+init): U_w -> bf16 hi/lo, swizzled ----------
__global__ __launch_bounds__(128) void wsplit_kernel(const float* __restrict__ Uw) {
    int bx = blockIdx.x;
    int r = bx / 12, c = bx % 12;
    int t = threadIdx.x;
    if (bx == 0 && t < RSZ) { g_cnt[t] = 0; g_probsum[t] = 0.f; }
    int wrow = t >> 1, whalf = t & 1;
    const float* src = Uw + ((size_t)r*DFULL + c*64 + wrow)*HSZ + whalf*32;
    char* dh = g_Wh + ((size_t)(r*12 + c))*8192;
    char* dl = g_Wl + ((size_t)(r*12 + c))*8192;
    uint32_t rowb = (uint32_t)(wrow*128 + whalf*64);
    uint32_t xorv = (uint32_t)(wrow & 7) << 4;
    #pragma unroll
    for (int q2 = 0; q2 < 4; q2++) {
        float4 v0 = ((const float4*)src)[2*q2];
        float4 v1 = ((const float4*)src)[2*q2 + 1];
        uint32_t h0,h1,h2,h3,l0,l1,l2,l3;
        split2(v0.x, v0.y, h0, l0); split2(v0.z, v0.w, h1, l1);
        split2(v1.x, v1.y, h2, l2); split2(v1.z, v1.w, h3, l3);
        uint32_t off = (rowb + q2*16) ^ xorv;
        *(uint4*)(dh + off) = make_uint4(h0,h1,h2,h3);
        *(uint4*)(dl + off) = make_uint4(l0,l1,l2,l3);
    }
}

// ---------------- Vl = l2norm(llm @ V_w[r] + V_b[r]); emit swizzled bf16 hi/lo -------
__global__ __launch_bounds__(64) void vl_kernel(const float* __restrict__ llm,
                                                const float* __restrict__ Vw,
                                                const float* __restrict__ Vb) {
    int l = blockIdx.x, r = blockIdx.y, h = threadIdx.x;
    __shared__ float lsm[DHALF];
    __shared__ float red[64];
    __shared__ float s_inv;
    for (int i = h; i < DHALF; i += 64) lsm[i] = llm[l*DHALF + i];
    __syncthreads();
    float acc = Vb[r*HSZ + h];
    const float* w = Vw + ((size_t)r*DHALF)*HSZ + h;
    #pragma unroll 8
    for (int d = 0; d < DHALF; d++) acc += lsm[d] * w[(size_t)d*HSZ];
    red[h] = acc*acc;
    __syncthreads();
    if (h == 0) {
        float ss = 0.f;
        #pragma unroll
        for (int i = 0; i < 64; i++) ss += red[i];
        s_inv = 1.f / fmaxf(sqrtf(ss), 1e-12f);
    }
    __syncthreads();
    float val = acc * s_inv;
    unsigned short hbits = __bfloat16_as_ushort(__float2bfloat16(val));
    float hf = __uint_as_float(((uint32_t)hbits) << 16);
    unsigned short lbits = __bfloat16_as_ushort(__float2bfloat16(val - hf));
    uint32_t off = (uint32_t)(h*128 + l*2) ^ ((uint32_t)(h & 7) << 4);
    *(unsigned short*)(g_VhSwz + r*8192 + off) = hbits;
    *(unsigned short*)(g_VlSwz + r*8192 + off) = lbits;
}

// ---------------- gate v5: lane = token; broadcast w; cp.async double buffer -------
#define GB 256
struct GateSmem {
    float Wt[RSZ][772];        // [r][k], warp-uniform reads (broadcast)
    float Xc[2][8][32][36];    // double-buffered per-warp x chunk (32 floats + pad)
    float pblk[8][RSZ];
    float bsm[RSZ];
    int   i1s[GB], i2s[GB];
    int   locs[2*GB];
    int   cnt2[16];
    int   bases[RSZ];
};

__global__ __launch_bounds__(256, 2) void gate_kernel(const float* __restrict__ posts,
                                                      const float* __restrict__ reas,
                                                      const float* __restrict__ gw,
                                                      const float* __restrict__ gb) {
    extern __shared__ char gsraw[];
    GateSmem& sh = *reinterpret_cast<GateSmem*>(gsraw);
    int t = threadIdx.x, lane = t & 31, w = t >> 5;
    int nblk = blockIdx.x * GB;
    int n = nblk + t;                       // this lane's token

    for (int i = t; i < DFULL*RSZ; i += 256) {
        int k = i >> 3, rr = i & 7;
        sh.Wt[rr][k] = gw[i];
    }
    if (t < RSZ) sh.bsm[t] = gb[t];

    uint32_t XcB = (uint32_t)__cvta_generic_to_shared(&sh.Xc[0][0][0][0]);
    int tokb = lane >> 3, fq = lane & 7;    // staging: 4 tokens x 8 float4 per phase

    auto stage = [&](int c, int buf) {
        const float* bsrc = (c < 12) ? posts : reas;
        int off = (c < 12) ? c*32 : (c - 12)*32;
        #pragma unroll
        for (int ii = 0; ii < 8; ii++) {
            int tok = ii*4 + tokb;
            const float* src = bsrc + (size_t)(nblk + w*32 + tok)*DHALF + off + 4*fq;
            uint32_t dst = XcB + (uint32_t)(((buf*8 + w)*32 + tok)*144 + 16*fq);
            cp16(dst, src);
        }
        asm volatile("cp.async.commit_group;" ::: "memory");
    };

    float acc[RSZ];
    #pragma unroll
    for (int r = 0; r < RSZ; r++) acc[r] = 0.f;

    stage(0, 0);
    __syncthreads();   // Wt/bsm ready (staging itself is warp-local via cp.async)

    for (int c = 0; c < 24; c++) {
        if (c + 1 < 24) {
            stage(c + 1, (c + 1) & 1);
            asm volatile("cp.async.wait_group 1;" ::: "memory");
        } else {
            asm volatile("cp.async.wait_group 0;" ::: "memory");
        }
        __syncwarp();
        int buf = c & 1;
        #pragma unroll
        for (int j4 = 0; j4 < 8; j4++) {
            float4 xv = *(const float4*)&sh.Xc[buf][w][lane][4*j4];
            #pragma unroll
            for (int r = 0; r < RSZ; r++) {
                float4 wv = *(const float4*)&sh.Wt[r][c*32 + 4*j4];
                acc[r] += xv.x*wv.x + xv.y*wv.y + xv.z*wv.z + xv.w*wv.w;
            }
        }
        __syncwarp();
    }

    float lg[RSZ];
    #pragma unroll
    for (int r = 0; r < RSZ; r++) lg[r] = acc[r] + sh.bsm[r];

    // serial top-2 (strict >, earlier index wins ties — matches jax top_k)
    float v1 = -1e30f, v2 = -1e30f; int i1 = 0, i2 = 0;
    #pragma unroll
    for (int r = 0; r < RSZ; r++) {
        if (lg[r] > v1)      { v2 = v1; i2 = i1; v1 = lg[r]; i1 = r; }
        else if (lg[r] > v2) { v2 = lg[r]; i2 = r; }
    }
    // softmax over 8 routers (aux probsum)
    float p[RSZ], s = 0.f;
    #pragma unroll
    for (int r = 0; r < RSZ; r++) { p[r] = expf(lg[r] - v1); s += p[r]; }
    float invs = 1.f / s;
    #pragma unroll
    for (int r = 0; r < RSZ; r++) {
        float q = p[r] * invs;
        q += __shfl_xor_sync(0xffffffffu, q, 16);
        q += __shfl_xor_sync(0xffffffffu, q, 8);
        q += __shfl_xor_sync(0xffffffffu, q, 4);
        q += __shfl_xor_sync(0xffffffffu, q, 2);
        q += __shfl_xor_sync(0xffffffffu, q, 1);
        if (lane == 0) sh.pblk[w][r] = q;
    }
    float g0 = 1.f / (1.f + expf(v2 - v1));
    g_gate[2*n]   = g0;
    g_gate[2*n+1] = 1.f - g0;
    sh.i1s[t] = i1; sh.i2s[t] = i2;
    __syncthreads();

    // stable compaction, 16 scanners (r, half)
    if (t < 16) {
        int r = t & 7, h = t >> 3;
        int c = 0;
        for (int e = h*GB; e < (h + 1)*GB; e++) {
            int rid = (e & 1) ? sh.i2s[e >> 1] : sh.i1s[e >> 1];
            if (rid == r) sh.locs[e] = c++;
        }
        sh.cnt2[t] = c;
    }
    __syncthreads();
    if (t < RSZ) sh.bases[t] = atomicAdd(&g_cnt[t], sh.cnt2[t] + sh.cnt2[t + 8]);
    __syncthreads();
    #pragma unroll
    for (int pass = 0; pass < 2; pass++) {
        int e = t + pass*256;
        int rid = (e & 1) ? sh.i2s[e >> 1] : sh.i1s[e >> 1];
        int off = sh.bases[rid] + sh.locs[e] + ((e >= GB) ? sh.cnt2[rid] : 0);
        g_list[rid*NTOK + off] = 2*(nblk + (e >> 1)) + (e & 1);
    }
    if (t < RSZ) {
        float sm = 0.f;
        #pragma unroll
        for (int wi = 0; wi < 8; wi++) sm += sh.pblk[wi][t];
        atomicAdd(&g_probsum[t], sm);
    }
}

// ---------------- proj: bf16x3 tensor MMA (round-11 proven shape) ----------------
struct ProjSmem {
    union {
        struct { char Ah[128*128]; char Al[128*128]; char Wh[64*128]; char Wl[64*128]; } m;
        struct { char Uh[128*128]; char Ul[128*128]; char Vh[64*128]; char Vl[64*128]; } e;
    } u;                                    // 48 KB
    int   el[128];
    float gwv[128];
    float bs[64];
};

__global__ __launch_bounds__(128, 3) void proj_kernel(const float* __restrict__ posts,
                                                      const float* __restrict__ reas,
                                                      const float* __restrict__ Ub) {
    int r = blockIdx.y;
    int cnt = g_cnt[r];
    int base = blockIdx.x * 128;
    if (base >= cnt) return;

    extern __shared__ char smraw[];
    ProjSmem& sh = *reinterpret_cast<ProjSmem*>(smraw);

    int t = threadIdx.x, lane = t & 31, w = t >> 5;
    const int R0 = 32*w;
    const int g  = lane >> 2;
    const int tq = lane & 3;

    {
        int i = base + t;
        int e = (i < cnt) ? g_list[r*NTOK + i] : g_list[r*NTOK + base];
        sh.el[t] = e;
        sh.gwv[t] = g_gate[e];
    }
    if (t < 64) sh.bs[t] = Ub[r*HSZ + t];
    __syncthreads();

    uint32_t AhB = (uint32_t)__cvta_generic_to_shared(sh.u.m.Ah);
    uint32_t AlB = (uint32_t)__cvta_generic_to_shared(sh.u.m.Al);
    uint32_t WhB = (uint32_t)__cvta_generic_to_shared(sh.u.m.Wh);
    uint32_t WlB = (uint32_t)__cvta_generic_to_shared(sh.u.m.Wl);

    const int half = lane >> 4, fq = lane & 15;
    int xrows[16];
    #pragma unroll
    for (int i = 0; i < 16; i++) xrows[i] = sh.el[32*w + 2*i + half] >> 1;

    float acc[2][8][4];
    #pragma unroll
    for (int T = 0; T < 2; T++)
        #pragma unroll
        for (int j = 0; j < 8; j++)
            #pragma unroll
            for (int q = 0; q < 4; q++) acc[T][j][q] = 0.f;

    for (int c = 0; c < 12; c++) {
        {
            const char* srcH = g_Wh + ((size_t)(r*12 + c))*8192 + t*64;
            const char* srcL = g_Wl + ((size_t)(r*12 + c))*8192 + t*64;
            uint32_t dH = WhB + t*64, dL = WlB + t*64;
            #pragma unroll
            for (int q = 0; q < 4; q++) {
                cp16(dH + 16*q, srcH + 16*q);
                cp16(dL + 16*q, srcL + 16*q);
            }
            asm volatile("cp.async.commit_group;" ::: "memory");
        }
        {
            const float* bsrc;
            int off_in;
            if (c < 6) { bsrc = posts; off_in = c*64; }
            else       { bsrc = reas;  off_in = (c - 6)*64; }
            #pragma unroll
            for (int i = 0; i < 16; i++) {
                int row = 32*w + 2*i + half;
                const float* src = bsrc + (size_t)xrows[i]*DHALF + off_in;
                float4 v = ((const float4*)src)[fq];
                uint32_t hp, lp, hp2, lp2;
                split2(v.x, v.y, hp, lp);
                split2(v.z, v.w, hp2, lp2);
                uint32_t off = ((uint32_t)row*128 + fq*8) ^ ((uint32_t)(row & 7) << 4);
                *(uint2*)(sh.u.m.Ah + off) = make_uint2(hp, hp2);
                *(uint2*)(sh.u.m.Al + off) = make_uint2(lp, lp2);
            }
        }
        asm volatile("cp.async.wait_group 0;" ::: "memory");
        __syncthreads();
        #pragma unroll
        for (int kk = 0; kk < 4; kk++) {
            int arow = R0 + (lane & 15);
            uint32_t asel = (uint32_t)(2*kk + (lane >> 4))*16;
            uint32_t aoff0 = ((uint32_t)arow*128 + asel) ^ ((uint32_t)(arow & 7) << 4);
            int arow1 = arow + 16;
            uint32_t aoff1 = ((uint32_t)arow1*128 + asel) ^ ((uint32_t)(arow1 & 7) << 4);
            uint32_t ah0[4], al0[4], ah1[4], al1[4];
            ldsm4(ah0, AhB + aoff0); ldsm4(al0, AlB + aoff0);
            ldsm4(ah1, AhB + aoff1); ldsm4(al1, AlB + aoff1);
            int krow = 16*kk + (lane & 15);
            uint32_t bxor = (uint32_t)(krow & 7) << 4;
            #pragma unroll
            for (int f = 0; f < 4; f++) {
                uint32_t boff = ((uint32_t)krow*128 + (2*f + (lane >> 4))*16) ^ bxor;
                uint32_t bh[4], bl[4];
                ldsm4t(bh, WhB + boff);
                mma16816(acc[0][2*f],     ah0, bh[0], bh[1]);
                mma16816(acc[0][2*f + 1], ah0, bh[2], bh[3]);
                mma16816(acc[0][2*f],     al0, bh[0], bh[1]);
                mma16816(acc[0][2*f + 1], al0, bh[2], bh[3]);
                mma16816(acc[1][2*f],     ah1, bh[0], bh[1]);
                mma16816(acc[1][2*f + 1], ah1, bh[2], bh[3]);
                mma16816(acc[1][2*f],     al1, bh[0], bh[1]);
                mma16816(acc[1][2*f + 1], al1, bh[2], bh[3]);
                ldsm4t(bl, WlB + boff);
                mma16816(acc[0][2*f],     ah0, bl[0], bl[1]);
                mma16816(acc[0][2*f + 1], ah0, bl[2], bl[3]);
                mma16816(acc[1][2*f],     ah1, bl[0], bl[1]);
                mma16816(acc[1][2*f + 1], ah1, bl[2], bl[3]);
            }
        }
        __syncthreads();
    }

    {
        const uint4* srcH = (const uint4*)(g_VhSwz + r*8192);
        const uint4* srcL = (const uint4*)(g_VlSwz + r*8192);
        #pragma unroll
        for (int q = 0; q < 4; q++) {
            ((uint4*)sh.u.e.Vh)[t + 128*q] = srcH[t + 128*q];
            ((uint4*)sh.u.e.Vl)[t + 128*q] = srcL[t + 128*q];
        }
    }

    float invn[2][2];
    #pragma unroll
    for (int T = 0; T < 2; T++) {
        float s0 = 0.f, s1 = 0.f;
        #pragma unroll
        for (int j = 0; j < 8; j++) {
            float b0 = sh.bs[8*j + 2*tq], b1 = sh.bs[8*j + 2*tq + 1];
            acc[T][j][0] += b0; acc[T][j][1] += b1;
            acc[T][j][2] += b0; acc[T][j][3] += b1;
            s0 += acc[T][j][0]*acc[T][j][0] + acc[T][j][1]*acc[T][j][1];
            s1 += acc[T][j][2]*acc[T][j][2] + acc[T][j][3]*acc[T][j][3];
        }
        s0 += __shfl_xor_sync(0xffffffffu, s0, 1);
        s0 += __shfl_xor_sync(0xffffffffu, s0, 2);
        s1 += __shfl_xor_sync(0xffffffffu, s1, 1);
        s1 += __shfl_xor_sync(0xffffffffu, s1, 2);
        invn[T][0] = 1.f / fmaxf(sqrtf(s0), 1e-12f);
        invn[T][1] = 1.f / fmaxf(sqrtf(s1), 1e-12f);
    }

    #pragma unroll
    for (int T = 0; T < 2; T++) {
        int rowA = R0 + 16*T + g, rowB = rowA + 8;
        uint32_t xorA = (uint32_t)(rowA & 7) << 4;
        uint32_t xorB = (uint32_t)(rowB & 7) << 4;
        #pragma unroll
        for (int j = 0; j < 8; j++) {
            uint32_t hp, lp;
            split2(acc[T][j][0]*invn[T][0], acc[T][j][1]*invn[T][0], hp, lp);
            uint32_t offA = ((uint32_t)rowA*128 + 16*j + 4*tq) ^ xorA;
            *(uint32_t*)(sh.u.e.Uh + offA) = hp;
            *(uint32_t*)(sh.u.e.Ul + offA) = lp;
            split2(acc[T][j][2]*invn[T][1], acc[T][j][3]*invn[T][1], hp, lp);
            uint32_t offB = ((uint32_t)rowB*128 + 16*j + 4*tq) ^ xorB;
            *(uint32_t*)(sh.u.e.Uh + offB) = hp;
            *(uint32_t*)(sh.u.e.Ul + offB) = lp;
        }
    }
    __syncthreads();

    uint32_t UhB = (uint32_t)__cvta_generic_to_shared(sh.u.e.Uh);
    uint32_t UlB = (uint32_t)__cvta_generic_to_shared(sh.u.e.Ul);
    uint32_t VhB = (uint32_t)__cvta_generic_to_shared(sh.u.e.Vh);
    uint32_t VlB = (uint32_t)__cvta_generic_to_shared(sh.u.e.Vl);
    #pragma unroll
    for (int T = 0; T < 2; T++)
        #pragma unroll
        for (int j = 0; j < 8; j++)
            #pragma unroll
            for (int q = 0; q < 4; q++) acc[T][j][q] = 0.f;
    #pragma unroll
    for (int kk = 0; kk < 4; kk++) {
        int arow = R0 + (lane & 15);
        uint32_t asel = (uint32_t)(2*kk + (lane >> 4))*16;
        uint32_t aoff0 = ((uint32_t)arow*128 + asel) ^ ((uint32_t)(arow & 7) << 4);
        int arow1 = arow + 16;
        uint32_t aoff1 = ((uint32_t)arow1*128 + asel) ^ ((uint32_t)(arow1 & 7) << 4);
        uint32_t ah0[4], al0[4], ah1[4], al1[4];
        ldsm4(ah0, UhB + aoff0); ldsm4(al0, UlB + aoff0);
        ldsm4(ah1, UhB + aoff1); ldsm4(al1, UlB + aoff1);
        int krow = 16*kk + (lane & 15);
        uint32_t bxor = (uint32_t)(krow & 7) << 4;
        #pragma unroll
        for (int f = 0; f < 4; f++) {
            uint32_t boff = ((uint32_t)krow*128 + (2*f + (lane >> 4))*16) ^ bxor;
            uint32_t bh[4], bl[4];
            ldsm4t(bh, VhB + boff);
            mma16816(acc[0][2*f],     ah0, bh[0], bh[1]);
            mma16816(acc[0][2*f + 1], ah0, bh[2], bh[3]);
            mma16816(acc[0][2*f],     al0, bh[0], bh[1]);
            mma16816(acc[0][2*f + 1], al0, bh[2], bh[3]);
            mma16816(acc[1][2*f],     ah1, bh[0], bh[1]);
            mma16816(acc[1][2*f + 1], ah1, bh[2], bh[3]);
            mma16816(acc[1][2*f],     al1, bh[0], bh[1]);
            mma16816(acc[1][2*f + 1], al1, bh[2], bh[3]);
            ldsm4t(bl, VlB + boff);
            mma16816(acc[0][2*f],     ah0, bl[0], bl[1]);
            mma16816(acc[0][2*f + 1], ah0, bl[2], bl[3]);
            mma16816(acc[1][2*f],     ah1, bl[0], bl[1]);
            mma16816(acc[1][2*f + 1], ah1, bl[2], bl[3]);
        }
    }

    #pragma unroll
    for (int T = 0; T < 2; T++) {
        float m0 = -1e30f, m1 = -1e30f;
        #pragma unroll
        for (int j = 0; j < 8; j++) {
            m0 = fmaxf(m0, fmaxf(acc[T][j][0], acc[T][j][1]));
            m1 = fmaxf(m1, fmaxf(acc[T][j][2], acc[T][j][3]));
        }
        m0 = fmaxf(m0, __shfl_xor_sync(0xffffffffu, m0, 1));
        m0 = fmaxf(m0, __shfl_xor_sync(0xffffffffu, m0, 2));
        m1 = fmaxf(m1, __shfl_xor_sync(0xffffffffu, m1, 1));
        m1 = fmaxf(m1, __shfl_xor_sync(0xffffffffu, m1, 2));
        float s0 = 0.f, s1 = 0.f;
        #pragma unroll
        for (int j = 0; j < 8; j++) {
            acc[T][j][0] = __expf(acc[T][j][0] - m0);
            acc[T][j][1] = __expf(acc[T][j][1] - m0);
            acc[T][j][2] = __expf(acc[T][j][2] - m1);
            acc[T][j][3] = __expf(acc[T][j][3] - m1);
            s0 += acc[T][j][0] + acc[T][j][1];
            s1 += acc[T][j][2] + acc[T][j][3];
        }
        s0 += __shfl_xor_sync(0xffffffffu, s0, 1);
        s0 += __shfl_xor_sync(0xffffffffu, s0, 2);
        s1 += __shfl_xor_sync(0xffffffffu, s1, 1);
        s1 += __shfl_xor_sync(0xffffffffu, s1, 2);
        int row0 = R0 + 16*T + g, row1 = row0 + 8;
        float sc0 = sh.gwv[row0] / s0;
        float sc1 = sh.gwv[row1] / s1;
        bool ok0 = (base + row0) < cnt;
        bool ok1 = (base + row1) < cnt;
        float* d0 = g_out + (size_t)sh.el[row0]*LSZ;
        float* d1 = g_out + (size_t)sh.el[row1]*LSZ;
        #pragma unroll
        for (int j = 0; j < 8; j++) {
            int col = 8*j + 2*tq;
            if (ok0) *(float2*)(d0 + col) = make_float2(acc[T][j][0]*sc0, acc[T][j][1]*sc0);
            if (ok1) *(float2*)(d1 + col) = make_float2(acc[T][j][2]*sc1, acc[T][j][3]*sc1);
        }
    }
}

// ---------------- sample (+aux): combine 2 entries, cumsum, pick, log -------------
__global__ __launch_bounds__(256) void sample_kernel(const float* __restrict__ rnd,
                                                     float* __restrict__ out_idx,
                                                     float* __restrict__ out_lp,
                                                     float* __restrict__ out_aux) {
    int t = threadIdx.x, lane = t & 31, w = t >> 5;
    if (blockIdx.x == 0 && t == 0) {
        float s = 0.f;
        #pragma unroll
        for (int r = 0; r < RSZ; r++)
            s += (g_probsum[r] / (float)NTOK) * ((float)g_cnt[r] / (float)NTOK);
        out_aux[0] = (float)RSZ * s * 0.05f;
    }
    int n = blockIdx.x*8 + w;
    const float* b = g_out + (size_t)2*n*LSZ;
    float v0 = b[lane]      + b[64 + lane];
    float v1 = b[32 + lane] + b[96 + lane];
    float rv = rnd[n];
    float s0 = v0;
    #pragma unroll
    for (int o = 1; o < 32; o <<= 1) {
        float u = __shfl_up_sync(0xffffffffu, s0, o);
        if (lane >= o) s0 += u;
    }
    float tot0 = __shfl_sync(0xffffffffu, s0, 31);
    float s1 = v1;
    #pragma unroll
    for (int o = 1; o < 32; o <<= 1) {
        float u = __shfl_up_sync(0xffffffffu, s1, o);
        if (lane >= o) s1 += u;
    }
    s1 += tot0;
    unsigned b0 = __ballot_sync(0xffffffffu, s0 > rv);
    unsigned b1 = __ballot_sync(0xffffffffu, s1 > rv);
    int sel = b0 ? (__ffs(b0) - 1) : (b1 ? (31 + __ffs(b1)) : 0);
    float p = (sel < 32) ? __shfl_sync(0xffffffffu, v0, sel)
                         : __shfl_sync(0xffffffffu, v1, sel - 32);
    if (lane == 0) {
        out_idx[n] = (float)sel;
        out_lp[n]  = logf(p);
    }
}

// ---------------- launch: side-stream overlap of (wsplit, vl) with gate ----------
extern "C" void kernel_launch(void* const* d_in, const int* in_sizes, int n_in,
                              void* d_out, int out_size) {
    const float* posts = (const float*)d_in[0];
    const float* reas  = (const float*)d_in[1];
    const float* llm   = (const float*)d_in[2];
    const float* rnd   = (const float*)d_in[3];
    const float* gw    = (const float*)d_in[4];
    const float* gb    = (const float*)d_in[5];
    const float* Uw    = (const float*)d_in[6];
    const float* Ub    = (const float*)d_in[7];
    const float* Vw    = (const float*)d_in[8];
    const float* Vb    = (const float*)d_in[9];
    float* out = (float*)d_out;

    static bool init_done = false;
    static cudaStream_t s2;
    static cudaEvent_t evFork, evJoin;
    if (!init_done) {
        cudaFuncSetAttribute(proj_kernel, cudaFuncAttributeMaxDynamicSharedMemorySize,
                             (int)sizeof(ProjSmem));
        cudaFuncSetAttribute(gate_kernel, cudaFuncAttributeMaxDynamicSharedMemorySize,
                             (int)sizeof(GateSmem));
        cudaStreamCreateWithFlags(&s2, cudaStreamNonBlocking);
        cudaEventCreateWithFlags(&evFork, cudaEventDisableTiming);
        cudaEventCreateWithFlags(&evJoin, cudaEventDisableTiming);
        init_done = true;
    }

    // fork: side stream runs wsplit + vl while main stream runs gate
    cudaEventRecord(evFork, 0);
    cudaStreamWaitEvent(s2, evFork, 0);
    wsplit_kernel<<<RSZ*12, 128, 0, s2>>>(Uw);
    vl_kernel<<<dim3(LSZ, RSZ), 64, 0, s2>>>(llm, Vw, Vb);
    cudaEventRecord(evJoin, s2);

    gate_kernel<<<NTOK/GB, 256, sizeof(GateSmem)>>>(posts, reas, gw, gb);

    // join: proj needs gate outputs (main stream) and wsplit/vl outputs (s2)
    cudaStreamWaitEvent(0, evJoin, 0);
    proj_kernel<<<dim3(NTOK/128, RSZ), 128, sizeof(ProjSmem)>>>(posts, reas, Ub);
    sample_kernel<<<NTOK/8, 256>>>(rnd, out, out + NTOK, out + 2*NTOK);
}

// round 16
// speedup vs baseline: 1.8672x; 1.0238x over previous
#include <cuda_runtime.h>
#include <cuda_bf16.h>
#include <math.h>
#include <stdint.h>

#define NTOK  65536
#define DHALF 384
#define DFULL 768
#define LSZ   64
#define HSZ   64
#define RSZ   8

// ---------------- device scratch (static; no allocations) ----------------
__device__ int   g_cnt[RSZ];
__device__ float g_probsum[RSZ];
__device__ int   g_list[RSZ*NTOK];              // entry e = 2*n + slot
__device__ float g_gate[2*NTOK];                // gate weight per entry
__device__ float g_out[(size_t)2*NTOK*LSZ];     // gate-scaled softmax scores per entry
// pre-split, pre-swizzled Vl (ldmatrix layout, [r] blocks of 64 rows x 128B)
__device__ __align__(16) char g_VhSwz[RSZ*8192];
__device__ __align__(16) char g_VlSwz[RSZ*8192];
// pre-split, pre-swizzled U_w: [r][chunk c<12] blocks of 64 k-rows x 128B
__device__ __align__(16) char g_Wh[RSZ*12*8192];
__device__ __align__(16) char g_Wl[RSZ*12*8192];

// ---------------- helpers ----------------
__device__ __forceinline__ uint32_t packbf(float lo, float hi) {
    uint32_t d;
    asm("cvt.rn.bf16x2.f32 %0, %1, %2;" : "=r"(d) : "f"(hi), "f"(lo));
    return d;
}
__device__ __forceinline__ void split2(float x0, float x1, uint32_t& hp, uint32_t& lp) {
    hp = packbf(x0, x1);
    float h0 = __uint_as_float(hp << 16);
    float h1 = __uint_as_float(hp & 0xffff0000u);
    lp = packbf(x0 - h0, x1 - h1);
}
__device__ __forceinline__ void ldsm4(uint32_t r[4], uint32_t addr) {
    asm volatile("ldmatrix.sync.aligned.m8n8.x4.shared.b16 {%0,%1,%2,%3}, [%4];"
        : "=r"(r[0]), "=r"(r[1]), "=r"(r[2]), "=r"(r[3]) : "r"(addr));
}
__device__ __forceinline__ void ldsm4t(uint32_t r[4], uint32_t addr) {
    asm volatile("ldmatrix.sync.aligned.m8n8.x4.trans.shared.b16 {%0,%1,%2,%3}, [%4];"
        : "=r"(r[0]), "=r"(r[1]), "=r"(r[2]), "=r"(r[3]) : "r"(addr));
}
__device__ __forceinline__ void mma16816(float c[4], const uint32_t a[4],
                                         uint32_t b0, uint32_t b1) {
    asm volatile("mma.sync.aligned.m16n8k16.row.col.f32.bf16.bf16.f32 "
        "{%0,%1,%2,%3}, {%4,%5,%6,%7}, {%8,%9}, {%0,%1,%2,%3};"
        : "+f"(c[0]), "+f"(c[1]), "+f"(c[2]), "+f"(c[3])
        : "r"(a[0]), "r"(a[1]), "r"(a[2]), "r"(a[3]), "r"(b0), "r"(b1));
}
__device__ __forceinline__ void cp16(uint32_t dst, const void* src) {
    asm volatile("cp.async.ca.shared.global [%0], [%1], 16;" :: "r"(dst), "l"(src));
}

// ---------------- W presplit (+init): U_w -> bf16 hi/lo, swizzled ----------
__global__ __launch_bounds__(128) void wsplit_kernel(const float* __restrict__ Uw) {
    int bx = blockIdx.x;
    int r = bx / 12, c = bx % 12;
    int t = threadIdx.x;
    if (bx == 0 && t < RSZ) { g_cnt[t] = 0; g_probsum[t] = 0.f; }
    int wrow = t >> 1, whalf = t & 1;
    const float* src = Uw + ((size_t)r*DFULL + c*64 + wrow)*HSZ + whalf*32;
    char* dh = g_Wh + ((size_t)(r*12 + c))*8192;
    char* dl = g_Wl + ((size_t)(r*12 + c))*8192;
    uint32_t rowb = (uint32_t)(wrow*128 + whalf*64);
    uint32_t xorv = (uint32_t)(wrow & 7) << 4;
    #pragma unroll
    for (int q2 = 0; q2 < 4; q2++) {
        float4 v0 = ((const float4*)src)[2*q2];
        float4 v1 = ((const float4*)src)[2*q2 + 1];
        uint32_t h0,h1,h2,h3,l0,l1,l2,l3;
        split2(v0.x, v0.y, h0, l0); split2(v0.z, v0.w, h1, l1);
        split2(v1.x, v1.y, h2, l2); split2(v1.z, v1.w, h3, l3);
        uint32_t off = (rowb + q2*16) ^ xorv;
        *(uint4*)(dh + off) = make_uint4(h0,h1,h2,h3);
        *(uint4*)(dl + off) = make_uint4(l0,l1,l2,l3);
    }
}

// ---------------- Vl = l2norm(llm @ V_w[r] + V_b[r]); emit swizzled bf16 hi/lo -------
__global__ __launch_bounds__(64) void vl_kernel(const float* __restrict__ llm,
                                                const float* __restrict__ Vw,
                                                const float* __restrict__ Vb) {
    int l = blockIdx.x, r = blockIdx.y, h = threadIdx.x;
    __shared__ float lsm[DHALF];
    __shared__ float red[64];
    __shared__ float s_inv;
    for (int i = h; i < DHALF; i += 64) lsm[i] = llm[l*DHALF + i];
    __syncthreads();
    float acc = Vb[r*HSZ + h];
    const float* w = Vw + ((size_t)r*DHALF)*HSZ + h;
    #pragma unroll 8
    for (int d = 0; d < DHALF; d++) acc += lsm[d] * w[(size_t)d*HSZ];
    red[h] = acc*acc;
    __syncthreads();
    if (h == 0) {
        float ss = 0.f;
        #pragma unroll
        for (int i = 0; i < 64; i++) ss += red[i];
        s_inv = 1.f / fmaxf(sqrtf(ss), 1e-12f);
    }
    __syncthreads();
    float val = acc * s_inv;
    unsigned short hbits = __bfloat16_as_ushort(__float2bfloat16(val));
    float hf = __uint_as_float(((uint32_t)hbits) << 16);
    unsigned short lbits = __bfloat16_as_ushort(__float2bfloat16(val - hf));
    uint32_t off = (uint32_t)(h*128 + l*2) ^ ((uint32_t)(h & 7) << 4);
    *(unsigned short*)(g_VhSwz + r*8192 + off) = hbits;
    *(unsigned short*)(g_VlSwz + r*8192 + off) = lbits;
}

// ---------------- gate v5: lane = token; broadcast w; cp.async double buffer -------
#define GB 256
struct GateSmem {
    float Wt[RSZ][772];        // [r][k], warp-uniform reads (broadcast)
    float Xc[2][8][32][36];    // double-buffered per-warp x chunk (32 floats + pad)
    float pblk[8][RSZ];
    float bsm[RSZ];
    int   i1s[GB], i2s[GB];
    int   locs[2*GB];
    int   cnt2[16];
    int   bases[RSZ];
};

__global__ __launch_bounds__(256, 2) void gate_kernel(const float* __restrict__ posts,
                                                      const float* __restrict__ reas,
                                                      const float* __restrict__ gw,
                                                      const float* __restrict__ gb) {
    extern __shared__ char gsraw[];
    GateSmem& sh = *reinterpret_cast<GateSmem*>(gsraw);
    int t = threadIdx.x, lane = t & 31, w = t >> 5;
    int nblk = blockIdx.x * GB;
    int n = nblk + t;                       // this lane's token

    for (int i = t; i < DFULL*RSZ; i += 256) {
        int k = i >> 3, rr = i & 7;
        sh.Wt[rr][k] = gw[i];
    }
    if (t < RSZ) sh.bsm[t] = gb[t];

    uint32_t XcB = (uint32_t)__cvta_generic_to_shared(&sh.Xc[0][0][0][0]);
    int tokb = lane >> 3, fq = lane & 7;    // staging: 4 tokens x 8 float4 per phase

    auto stage = [&](int c, int buf) {
        const float* bsrc = (c < 12) ? posts : reas;
        int off = (c < 12) ? c*32 : (c - 12)*32;
        #pragma unroll
        for (int ii = 0; ii < 8; ii++) {
            int tok = ii*4 + tokb;
            const float* src = bsrc + (size_t)(nblk + w*32 + tok)*DHALF + off + 4*fq;
            uint32_t dst = XcB + (uint32_t)(((buf*8 + w)*32 + tok)*144 + 16*fq);
            cp16(dst, src);
        }
        asm volatile("cp.async.commit_group;" ::: "memory");
    };

    float acc[RSZ];
    #pragma unroll
    for (int r = 0; r < RSZ; r++) acc[r] = 0.f;

    stage(0, 0);
    __syncthreads();   // Wt/bsm ready (staging itself is warp-local via cp.async)

    for (int c = 0; c < 24; c++) {
        if (c + 1 < 24) {
            stage(c + 1, (c + 1) & 1);
            asm volatile("cp.async.wait_group 1;" ::: "memory");
        } else {
            asm volatile("cp.async.wait_group 0;" ::: "memory");
        }
        __syncwarp();
        int buf = c & 1;
        #pragma unroll
        for (int j4 = 0; j4 < 8; j4++) {
            float4 xv = *(const float4*)&sh.Xc[buf][w][lane][4*j4];
            #pragma unroll
            for (int r = 0; r < RSZ; r++) {
                float4 wv = *(const float4*)&sh.Wt[r][c*32 + 4*j4];
                acc[r] += xv.x*wv.x + xv.y*wv.y + xv.z*wv.z + xv.w*wv.w;
            }
        }
        __syncwarp();
    }

    float lg[RSZ];
    #pragma unroll
    for (int r = 0; r < RSZ; r++) lg[r] = acc[r] + sh.bsm[r];

    // serial top-2 (strict >, earlier index wins ties — matches jax top_k)
    float v1 = -1e30f, v2 = -1e30f; int i1 = 0, i2 = 0;
    #pragma unroll
    for (int r = 0; r < RSZ; r++) {
        if (lg[r] > v1)      { v2 = v1; i2 = i1; v1 = lg[r]; i1 = r; }
        else if (lg[r] > v2) { v2 = lg[r]; i2 = r; }
    }
    // softmax over 8 routers (aux probsum)
    float p[RSZ], s = 0.f;
    #pragma unroll
    for (int r = 0; r < RSZ; r++) { p[r] = expf(lg[r] - v1); s += p[r]; }
    float invs = 1.f / s;
    #pragma unroll
    for (int r = 0; r < RSZ; r++) {
        float q = p[r] * invs;
        q += __shfl_xor_sync(0xffffffffu, q, 16);
        q += __shfl_xor_sync(0xffffffffu, q, 8);
        q += __shfl_xor_sync(0xffffffffu, q, 4);
        q += __shfl_xor_sync(0xffffffffu, q, 2);
        q += __shfl_xor_sync(0xffffffffu, q, 1);
        if (lane == 0) sh.pblk[w][r] = q;
    }
    float g0 = 1.f / (1.f + expf(v2 - v1));
    g_gate[2*n]   = g0;
    g_gate[2*n+1] = 1.f - g0;
    sh.i1s[t] = i1; sh.i2s[t] = i2;
    __syncthreads();

    // stable compaction, 16 scanners (r, half)
    if (t < 16) {
        int r = t & 7, h = t >> 3;
        int c = 0;
        for (int e = h*GB; e < (h + 1)*GB; e++) {
            int rid = (e & 1) ? sh.i2s[e >> 1] : sh.i1s[e >> 1];
            if (rid == r) sh.locs[e] = c++;
        }
        sh.cnt2[t] = c;
    }
    __syncthreads();
    if (t < RSZ) sh.bases[t] = atomicAdd(&g_cnt[t], sh.cnt2[t] + sh.cnt2[t + 8]);
    __syncthreads();
    #pragma unroll
    for (int pass = 0; pass < 2; pass++) {
        int e = t + pass*256;
        int rid = (e & 1) ? sh.i2s[e >> 1] : sh.i1s[e >> 1];
        int off = sh.bases[rid] + sh.locs[e] + ((e >= GB) ? sh.cnt2[rid] : 0);
        g_list[rid*NTOK + off] = 2*(nblk + (e >> 1)) + (e & 1);
    }
    if (t < RSZ) {
        float sm = 0.f;
        #pragma unroll
        for (int wi = 0; wi < 8; wi++) sm += sh.pblk[wi][t];
        atomicAdd(&g_probsum[t], sm);
    }
}

// ---------------- proj: bf16x3 tensor MMA + L2 prefetch of next X chunk ----------
struct ProjSmem {
    union {
        struct { char Ah[128*128]; char Al[128*128]; char Wh[64*128]; char Wl[64*128]; } m;
        struct { char Uh[128*128]; char Ul[128*128]; char Vh[64*128]; char Vl[64*128]; } e;
    } u;                                    // 48 KB
    int   el[128];
    float gwv[128];
    float bs[64];
};

__global__ __launch_bounds__(128, 3) void proj_kernel(const float* __restrict__ posts,
                                                      const float* __restrict__ reas,
                                                      const float* __restrict__ Ub) {
    int r = blockIdx.y;
    int cnt = g_cnt[r];
    int base = blockIdx.x * 128;
    if (base >= cnt) return;

    extern __shared__ char smraw[];
    ProjSmem& sh = *reinterpret_cast<ProjSmem*>(smraw);

    int t = threadIdx.x, lane = t & 31, w = t >> 5;
    const int R0 = 32*w;
    const int g  = lane >> 2;
    const int tq = lane & 3;

    {
        int i = base + t;
        int e = (i < cnt) ? g_list[r*NTOK + i] : g_list[r*NTOK + base];
        sh.el[t] = e;
        sh.gwv[t] = g_gate[e];
    }
    if (t < 64) sh.bs[t] = Ub[r*HSZ + t];
    __syncthreads();

    uint32_t AhB = (uint32_t)__cvta_generic_to_shared(sh.u.m.Ah);
    uint32_t AlB = (uint32_t)__cvta_generic_to_shared(sh.u.m.Al);
    uint32_t WhB = (uint32_t)__cvta_generic_to_shared(sh.u.m.Wh);
    uint32_t WlB = (uint32_t)__cvta_generic_to_shared(sh.u.m.Wl);

    const int half = lane >> 4, fq = lane & 15;
    int xrows[16];
    #pragma unroll
    for (int i = 0; i < 16; i++) xrows[i] = sh.el[32*w + 2*i + half] >> 1;

    // L2 prefetch of chunk 0
    {
        #pragma unroll
        for (int i = 0; i < 16; i++) {
            const float* p = posts + (size_t)xrows[i]*DHALF + 4*fq;
            asm volatile("prefetch.global.L2 [%0];" :: "l"(p));
        }
    }

    float acc[2][8][4];
    #pragma unroll
    for (int T = 0; T < 2; T++)
        #pragma unroll
        for (int j = 0; j < 8; j++)
            #pragma unroll
            for (int q = 0; q < 4; q++) acc[T][j][q] = 0.f;

    for (int c = 0; c < 12; c++) {
        {
            const char* srcH = g_Wh + ((size_t)(r*12 + c))*8192 + t*64;
            const char* srcL = g_Wl + ((size_t)(r*12 + c))*8192 + t*64;
            uint32_t dH = WhB + t*64, dL = WlB + t*64;
            #pragma unroll
            for (int q = 0; q < 4; q++) {
                cp16(dH + 16*q, srcH + 16*q);
                cp16(dL + 16*q, srcL + 16*q);
            }
            asm volatile("cp.async.commit_group;" ::: "memory");
        }
        {
            const float* bsrc;
            int off_in;
            if (c < 6) { bsrc = posts; off_in = c*64; }
            else       { bsrc = reas;  off_in = (c - 6)*64; }
            #pragma unroll
            for (int i = 0; i < 16; i++) {
                int row = 32*w + 2*i + half;
                const float* src = bsrc + (size_t)xrows[i]*DHALF + off_in;
                float4 v = ((const float4*)src)[fq];
                uint32_t hp, lp, hp2, lp2;
                split2(v.x, v.y, hp, lp);
                split2(v.z, v.w, hp2, lp2);
                uint32_t off = ((uint32_t)row*128 + fq*8) ^ ((uint32_t)(row & 7) << 4);
                *(uint2*)(sh.u.m.Ah + off) = make_uint2(hp, hp2);
                *(uint2*)(sh.u.m.Al + off) = make_uint2(lp, lp2);
            }
        }
        asm volatile("cp.async.wait_group 0;" ::: "memory");
        __syncthreads();
        // ---- L2 prefetch for chunk c+1 (rides under mma phase) ----
        if (c + 1 < 12) {
            const float* bsrc2;
            int off2;
            if (c + 1 < 6) { bsrc2 = posts; off2 = (c + 1)*64; }
            else           { bsrc2 = reas;  off2 = (c + 1 - 6)*64; }
            #pragma unroll
            for (int i = 0; i < 16; i++) {
                const float* p = bsrc2 + (size_t)xrows[i]*DHALF + off2 + 4*fq;
                asm volatile("prefetch.global.L2 [%0];" :: "l"(p));
            }
        }
        #pragma unroll
        for (int kk = 0; kk < 4; kk++) {
            int arow = R0 + (lane & 15);
            uint32_t asel = (uint32_t)(2*kk + (lane >> 4))*16;
            uint32_t aoff0 = ((uint32_t)arow*128 + asel) ^ ((uint32_t)(arow & 7) << 4);
            int arow1 = arow + 16;
            uint32_t aoff1 = ((uint32_t)arow1*128 + asel) ^ ((uint32_t)(arow1 & 7) << 4);
            uint32_t ah0[4], al0[4], ah1[4], al1[4];
            ldsm4(ah0, AhB + aoff0); ldsm4(al0, AlB + aoff0);
            ldsm4(ah1, AhB + aoff1); ldsm4(al1, AlB + aoff1);
            int krow = 16*kk + (lane & 15);
            uint32_t bxor = (uint32_t)(krow & 7) << 4;
            #pragma unroll
            for (int f = 0; f < 4; f++) {
                uint32_t boff = ((uint32_t)krow*128 + (2*f + (lane >> 4))*16) ^ bxor;
                uint32_t bh[4], bl[4];
                ldsm4t(bh, WhB + boff);
                mma16816(acc[0][2*f],     ah0, bh[0], bh[1]);
                mma16816(acc[0][2*f + 1], ah0, bh[2], bh[3]);
                mma16816(acc[0][2*f],     al0, bh[0], bh[1]);
                mma16816(acc[0][2*f + 1], al0, bh[2], bh[3]);
                mma16816(acc[1][2*f],     ah1, bh[0], bh[1]);
                mma16816(acc[1][2*f + 1], ah1, bh[2], bh[3]);
                mma16816(acc[1][2*f],     al1, bh[0], bh[1]);
                mma16816(acc[1][2*f + 1], al1, bh[2], bh[3]);
                ldsm4t(bl, WlB + boff);
                mma16816(acc[0][2*f],     ah0, bl[0], bl[1]);
                mma16816(acc[0][2*f + 1], ah0, bl[2], bl[3]);
                mma16816(acc[1][2*f],     ah1, bl[0], bl[1]);
                mma16816(acc[1][2*f + 1], ah1, bl[2], bl[3]);
            }
        }
        __syncthreads();
    }

    {
        const uint4* srcH = (const uint4*)(g_VhSwz + r*8192);
        const uint4* srcL = (const uint4*)(g_VlSwz + r*8192);
        #pragma unroll
        for (int q = 0; q < 4; q++) {
            ((uint4*)sh.u.e.Vh)[t + 128*q] = srcH[t + 128*q];
            ((uint4*)sh.u.e.Vl)[t + 128*q] = srcL[t + 128*q];
        }
    }

    float invn[2][2];
    #pragma unroll
    for (int T = 0; T < 2; T++) {
        float s0 = 0.f, s1 = 0.f;
        #pragma unroll
        for (int j = 0; j < 8; j++) {
            float b0 = sh.bs[8*j + 2*tq], b1 = sh.bs[8*j + 2*tq + 1];
            acc[T][j][0] += b0; acc[T][j][1] += b1;
            acc[T][j][2] += b0; acc[T][j][3] += b1;
            s0 += acc[T][j][0]*acc[T][j][0] + acc[T][j][1]*acc[T][j][1];
            s1 += acc[T][j][2]*acc[T][j][2] + acc[T][j][3]*acc[T][j][3];
        }
        s0 += __shfl_xor_sync(0xffffffffu, s0, 1);
        s0 += __shfl_xor_sync(0xffffffffu, s0, 2);
        s1 += __shfl_xor_sync(0xffffffffu, s1, 1);
        s1 += __shfl_xor_sync(0xffffffffu, s1, 2);
        invn[T][0] = 1.f / fmaxf(sqrtf(s0), 1e-12f);
        invn[T][1] = 1.f / fmaxf(sqrtf(s1), 1e-12f);
    }

    #pragma unroll
    for (int T = 0; T < 2; T++) {
        int rowA = R0 + 16*T + g, rowB = rowA + 8;
        uint32_t xorA = (uint32_t)(rowA & 7) << 4;
        uint32_t xorB = (uint32_t)(rowB & 7) << 4;
        #pragma unroll
        for (int j = 0; j < 8; j++) {
            uint32_t hp, lp;
            split2(acc[T][j][0]*invn[T][0], acc[T][j][1]*invn[T][0], hp, lp);
            uint32_t offA = ((uint32_t)rowA*128 + 16*j + 4*tq) ^ xorA;
            *(uint32_t*)(sh.u.e.Uh + offA) = hp;
            *(uint32_t*)(sh.u.e.Ul + offA) = lp;
            split2(acc[T][j][2]*invn[T][1], acc[T][j][3]*invn[T][1], hp, lp);
            uint32_t offB = ((uint32_t)rowB*128 + 16*j + 4*tq) ^ xorB;
            *(uint32_t*)(sh.u.e.Uh + offB) = hp;
            *(uint32_t*)(sh.u.e.Ul + offB) = lp;
        }
    }
    __syncthreads();

    uint32_t UhB = (uint32_t)__cvta_generic_to_shared(sh.u.e.Uh);
    uint32_t UlB = (uint32_t)__cvta_generic_to_shared(sh.u.e.Ul);
    uint32_t VhB = (uint32_t)__cvta_generic_to_shared(sh.u.e.Vh);
    uint32_t VlB = (uint32_t)__cvta_generic_to_shared(sh.u.e.Vl);
    #pragma unroll
    for (int T = 0; T < 2; T++)
        #pragma unroll
        for (int j = 0; j < 8; j++)
            #pragma unroll
            for (int q = 0; q < 4; q++) acc[T][j][q] = 0.f;
    #pragma unroll
    for (int kk = 0; kk < 4; kk++) {
        int arow = R0 + (lane & 15);
        uint32_t asel = (uint32_t)(2*kk + (lane >> 4))*16;
        uint32_t aoff0 = ((uint32_t)arow*128 + asel) ^ ((uint32_t)(arow & 7) << 4);
        int arow1 = arow + 16;
        uint32_t aoff1 = ((uint32_t)arow1*128 + asel) ^ ((uint32_t)(arow1 & 7) << 4);
        uint32_t ah0[4], al0[4], ah1[4], al1[4];
        ldsm4(ah0, UhB + aoff0); ldsm4(al0, UlB + aoff0);
        ldsm4(ah1, UhB + aoff1); ldsm4(al1, UlB + aoff1);
        int krow = 16*kk + (lane & 15);
        uint32_t bxor = (uint32_t)(krow & 7) << 4;
        #pragma unroll
        for (int f = 0; f < 4; f++) {
            uint32_t boff = ((uint32_t)krow*128 + (2*f + (lane >> 4))*16) ^ bxor;
            uint32_t bh[4], bl[4];
            ldsm4t(bh, VhB + boff);
            mma16816(acc[0][2*f],     ah0, bh[0], bh[1]);
            mma16816(acc[0][2*f + 1], ah0, bh[2], bh[3]);
            mma16816(acc[0][2*f],     al0, bh[0], bh[1]);
            mma16816(acc[0][2*f + 1], al0, bh[2], bh[3]);
            mma16816(acc[1][2*f],     ah1, bh[0], bh[1]);
            mma16816(acc[1][2*f + 1], ah1, bh[2], bh[3]);
            mma16816(acc[1][2*f],     al1, bh[0], bh[1]);
            mma16816(acc[1][2*f + 1], al1, bh[2], bh[3]);
            ldsm4t(bl, VlB + boff);
            mma16816(acc[0][2*f],     ah0, bl[0], bl[1]);
            mma16816(acc[0][2*f + 1], ah0, bl[2], bl[3]);
            mma16816(acc[1][2*f],     ah1, bl[0], bl[1]);
            mma16816(acc[1][2*f + 1], ah1, bl[2], bl[3]);
        }
    }

    #pragma unroll
    for (int T = 0; T < 2; T++) {
        float m0 = -1e30f, m1 = -1e30f;
        #pragma unroll
        for (int j = 0; j < 8; j++) {
            m0 = fmaxf(m0, fmaxf(acc[T][j][0], acc[T][j][1]));
            m1 = fmaxf(m1, fmaxf(acc[T][j][2], acc[T][j][3]));
        }
        m0 = fmaxf(m0, __shfl_xor_sync(0xffffffffu, m0, 1));
        m0 = fmaxf(m0, __shfl_xor_sync(0xffffffffu, m0, 2));
        m1 = fmaxf(m1, __shfl_xor_sync(0xffffffffu, m1, 1));
        m1 = fmaxf(m1, __shfl_xor_sync(0xffffffffu, m1, 2));
        float s0 = 0.f, s1 = 0.f;
        #pragma unroll
        for (int j = 0; j < 8; j++) {
            acc[T][j][0] = __expf(acc[T][j][0] - m0);
            acc[T][j][1] = __expf(acc[T][j][1] - m0);
            acc[T][j][2] = __expf(acc[T][j][2] - m1);
            acc[T][j][3] = __expf(acc[T][j][3] - m1);
            s0 += acc[T][j][0] + acc[T][j][1];
            s1 += acc[T][j][2] + acc[T][j][3];
        }
        s0 += __shfl_xor_sync(0xffffffffu, s0, 1);
        s0 += __shfl_xor_sync(0xffffffffu, s0, 2);
        s1 += __shfl_xor_sync(0xffffffffu, s1, 1);
        s1 += __shfl_xor_sync(0xffffffffu, s1, 2);
        int row0 = R0 + 16*T + g, row1 = row0 + 8;
        float sc0 = sh.gwv[row0] / s0;
        float sc1 = sh.gwv[row1] / s1;
        bool ok0 = (base + row0) < cnt;
        bool ok1 = (base + row1) < cnt;
        float* d0 = g_out + (size_t)sh.el[row0]*LSZ;
        float* d1 = g_out + (size_t)sh.el[row1]*LSZ;
        #pragma unroll
        for (int j = 0; j < 8; j++) {
            int col = 8*j + 2*tq;
            if (ok0) *(float2*)(d0 + col) = make_float2(acc[T][j][0]*sc0, acc[T][j][1]*sc0);
            if (ok1) *(float2*)(d1 + col) = make_float2(acc[T][j][2]*sc1, acc[T][j][3]*sc1);
        }
    }
}

// ---------------- sample (+aux): combine 2 entries, cumsum, pick, log -------------
__global__ __launch_bounds__(256) void sample_kernel(const float* __restrict__ rnd,
                                                     float* __restrict__ out_idx,
                                                     float* __restrict__ out_lp,
                                                     float* __restrict__ out_aux) {
    int t = threadIdx.x, lane = t & 31, w = t >> 5;
    if (blockIdx.x == 0 && t == 0) {
        float s = 0.f;
        #pragma unroll
        for (int r = 0; r < RSZ; r++)
            s += (g_probsum[r] / (float)NTOK) * ((float)g_cnt[r] / (float)NTOK);
        out_aux[0] = (float)RSZ * s * 0.05f;
    }
    int n = blockIdx.x*8 + w;
    const float* b = g_out + (size_t)2*n*LSZ;
    float v0 = b[lane]      + b[64 + lane];
    float v1 = b[32 + lane] + b[96 + lane];
    float rv = rnd[n];
    float s0 = v0;
    #pragma unroll
    for (int o = 1; o < 32; o <<= 1) {
        float u = __shfl_up_sync(0xffffffffu, s0, o);
        if (lane >= o) s0 += u;
    }
    float tot0 = __shfl_sync(0xffffffffu, s0, 31);
    float s1 = v1;
    #pragma unroll
    for (int o = 1; o < 32; o <<= 1) {
        float u = __shfl_up_sync(0xffffffffu, s1, o);
        if (lane >= o) s1 += u;
    }
    s1 += tot0;
    unsigned b0 = __ballot_sync(0xffffffffu, s0 > rv);
    unsigned b1 = __ballot_sync(0xffffffffu, s1 > rv);
    int sel = b0 ? (__ffs(b0) - 1) : (b1 ? (31 + __ffs(b1)) : 0);
    float p = (sel < 32) ? __shfl_sync(0xffffffffu, v0, sel)
                         : __shfl_sync(0xffffffffu, v1, sel - 32);
    if (lane == 0) {
        out_idx[n] = (float)sel;
        out_lp[n]  = logf(p);
    }
}

// ---------------- launch: side-stream overlap of (wsplit, vl) with gate ----------
extern "C" void kernel_launch(void* const* d_in, const int* in_sizes, int n_in,
                              void* d_out, int out_size) {
    const float* posts = (const float*)d_in[0];
    const float* reas  = (const float*)d_in[1];
    const float* llm   = (const float*)d_in[2];
    const float* rnd   = (const float*)d_in[3];
    const float* gw    = (const float*)d_in[4];
    const float* gb    = (const float*)d_in[5];
    const float* Uw    = (const float*)d_in[6];
    const float* Ub    = (const float*)d_in[7];
    const float* Vw    = (const float*)d_in[8];
    const float* Vb    = (const float*)d_in[9];
    float* out = (float*)d_out;

    static bool init_done = false;
    static cudaStream_t s2;
    static cudaEvent_t evFork, evJoin;
    if (!init_done) {
        cudaFuncSetAttribute(proj_kernel, cudaFuncAttributeMaxDynamicSharedMemorySize,
                             (int)sizeof(ProjSmem));
        cudaFuncSetAttribute(gate_kernel, cudaFuncAttributeMaxDynamicSharedMemorySize,
                             (int)sizeof(GateSmem));
        cudaStreamCreateWithFlags(&s2, cudaStreamNonBlocking);
        cudaEventCreateWithFlags(&evFork, cudaEventDisableTiming);
        cudaEventCreateWithFlags(&evJoin, cudaEventDisableTiming);
        init_done = true;
    }

    // fork: side stream runs wsplit + vl while main stream runs gate
    cudaEventRecord(evFork, 0);
    cudaStreamWaitEvent(s2, evFork, 0);
    wsplit_kernel<<<RSZ*12, 128, 0, s2>>>(Uw);
    vl_kernel<<<dim3(LSZ, RSZ), 64, 0, s2>>>(llm, Vw, Vb);
    cudaEventRecord(evJoin, s2);

    gate_kernel<<<NTOK/GB, 256, sizeof(GateSmem)>>>(posts, reas, gw, gb);

    // join: proj needs gate outputs (main stream) and wsplit/vl outputs (s2)
    cudaStreamWaitEvent(0, evJoin, 0);
    proj_kernel<<<dim3(NTOK/128, RSZ), 128, sizeof(ProjSmem)>>>(posts, reas, Ub);
    sample_kernel<<<NTOK/8, 256>>>(rnd, out, out + NTOK, out + 2*NTOK);
}